// round 3
// baseline (speedup 1.0000x reference)
#include <cuda_runtime.h>
#include <cuda_bf16.h>

// ---------------------------------------------------------------------------
// RGCN layer, 4-kernel pipeline:
//   memset : zero relation counters + in-degree
//   phase1 : basis expansion | per-node hs/ht (A_src@feat + A_b, A_tgt@feat)
//            | relation histogram (smem-aggregated) + degree histogram
//   phase2 : scan(rel counts) | out init = deg * (feat @ slw)
//            | per-edge attention scalar att[e]
//   scatter: block-aggregated counting-sort of edges by relation
//   main   : per-relation blocks, rel_w column in regs, msg*att, red.v4
// ---------------------------------------------------------------------------

#define IN_DIM 32
#define RMAX   256
#define NMAX   16384
#define EMAX   262144

__device__ float g_relw[RMAX * 1024];     // expanded per-relation weights
__device__ float g_hs[NMAX * IN_DIM];     // A_src @ feat + A_b
__device__ float g_ht[NMAX * IN_DIM];     // A_tgt @ feat
__device__ float g_att[EMAX];             // per-edge attention scalar
__device__ int   g_perm[EMAX];
__device__ int   g_off[RMAX + 1];
__device__ int   g_cur[RMAX];
struct Counters { int cnt[RMAX]; int deg[NMAX]; };
__device__ Counters g_c;

// ---- phase 1 ----------------------------------------------------------------
__global__ void __launch_bounds__(256)
k_phase1(const float* __restrict__ weight,   // [NB,32,32]
         const float* __restrict__ w_comp,   // [R,NB]
         const float* __restrict__ node_feat,// [N,32]
         const float* __restrict__ A_w,      // [32,128]
         const float* __restrict__ A_b,      // [32]
         const int*   __restrict__ edges,    // [2,E]
         const int*   __restrict__ rels,     // [E]
         int NB, int R, int N, int E, int nbNode)
{
    int b = blockIdx.x;

    if (b < R) {                                   // --- basis expansion ---
        const float* wc = w_comp + b * NB;
        for (int io = threadIdx.x; io < 1024; io += 256) {
            float acc = 0.f;
            for (int k = 0; k < NB; ++k)
                acc = fmaf(__ldg(wc + k), __ldg(weight + k * 1024 + io), acc);
            g_relw[b * 1024 + io] = acc;
        }
        return;
    }
    b -= R;

    if (b < nbNode) {                              // --- node hs / ht ---
        const int lane = threadIdx.x & 31;
        const int warp = threadIdx.x >> 5;
        float aws[32], awt[32];
#pragma unroll
        for (int i = 0; i < 32; ++i) {
            aws[i] = __ldg(A_w + lane * 128 + i);
            awt[i] = __ldg(A_w + lane * 128 + 32 + i);
        }
        const float ab = __ldg(A_b + lane);
        const int n = b * 8 + warp;
        if (n < N) {
            const float4* fp = (const float4*)(node_feat + (size_t)n * 32);
            float hs = ab, ht = 0.f;
#pragma unroll
            for (int c = 0; c < 8; ++c) {
                float4 f = __ldg(fp + c);
                hs = fmaf(f.x, aws[4*c+0], hs); ht = fmaf(f.x, awt[4*c+0], ht);
                hs = fmaf(f.y, aws[4*c+1], hs); ht = fmaf(f.y, awt[4*c+1], ht);
                hs = fmaf(f.z, aws[4*c+2], hs); ht = fmaf(f.z, awt[4*c+2], ht);
                hs = fmaf(f.w, aws[4*c+3], hs); ht = fmaf(f.w, awt[4*c+3], ht);
            }
            g_hs[(size_t)n * 32 + lane] = hs;
            g_ht[(size_t)n * 32 + lane] = ht;
        }
        return;
    }
    b -= nbNode;

    // --- histogram: relations (smem-aggregated) + in-degree (spread) ---
    __shared__ int sh[RMAX];
    for (int i = threadIdx.x; i < RMAX; i += 256) sh[i] = 0;
    __syncthreads();
    const int base = b * 4096;
#pragma unroll
    for (int k = 0; k < 16; ++k) {
        int e = base + k * 256 + threadIdx.x;
        if (e < E) {
            atomicAdd(&sh[__ldg(rels + e)], 1);
            atomicAdd(&g_c.deg[__ldg(edges + E + e)], 1);
        }
    }
    __syncthreads();
    for (int i = threadIdx.x; i < RMAX; i += 256) {
        int v = sh[i];
        if (v) atomicAdd(&g_c.cnt[i], v);
    }
}

// ---- phase 2 ----------------------------------------------------------------
__global__ void __launch_bounds__(256)
k_phase2(const float* __restrict__ node_feat,
         const float* __restrict__ slw,   // [32,32]
         const float* __restrict__ ttr,   // [E,32]
         const float* __restrict__ tre,   // [E,32]
         const float* __restrict__ A_w,   // [32,128]
         const float* __restrict__ B_w,   // [32]
         const float* __restrict__ B_b,   // [1]
         const int*   __restrict__ edges, // [2,E]
         float*       __restrict__ out,
         int R, int N, int E, int nbNode)
{
    int b = blockIdx.x;

    if (b == 0) {                                  // --- scan ---
        __shared__ int buf[RMAX];
        const int tid = threadIdx.x;
        int c = (tid < R) ? g_c.cnt[tid] : 0;
        buf[tid] = c;
        __syncthreads();
#pragma unroll
        for (int d = 1; d < RMAX; d <<= 1) {
            int v = (tid >= d) ? buf[tid - d] : 0;
            __syncthreads();
            buf[tid] += v;
            __syncthreads();
        }
        if (tid == 0) g_off[0] = 0;
        if (tid < R) { g_off[tid + 1] = buf[tid]; g_cur[tid] = buf[tid] - c; }
        return;
    }
    b -= 1;

    if (b < nbNode) {                              // --- out = deg*(feat@slw) ---
        const int lane = threadIdx.x & 31;
        const int warp = threadIdx.x >> 5;
        float slc[32];
#pragma unroll
        for (int i = 0; i < 32; ++i) slc[i] = __ldg(slw + i * 32 + lane);
        const int n = b * 8 + warp;
        if (n < N) {
            const float4* fp = (const float4*)(node_feat + (size_t)n * 32);
            float s0 = 0.f, s1 = 0.f;
#pragma unroll
            for (int c = 0; c < 8; ++c) {
                float4 f = __ldg(fp + c);
                s0 = fmaf(f.x, slc[4*c+0], s0); s1 = fmaf(f.y, slc[4*c+1], s1);
                s0 = fmaf(f.z, slc[4*c+2], s0); s1 = fmaf(f.w, slc[4*c+3], s1);
            }
            out[(size_t)n * 32 + lane] = (float)__ldg(&g_c.deg[n]) * (s0 + s1);
        }
        return;
    }
    b -= nbNode;

    // --- per-edge attention scalar ---
    const int lane = threadIdx.x & 31;
    float are[32], atr[32];
#pragma unroll
    for (int i = 0; i < 32; ++i) {
        are[i] = __ldg(A_w + lane * 128 + 64 + i);
        atr[i] = __ldg(A_w + lane * 128 + 96 + i);
    }
    const float bw = __ldg(B_w + lane);
    const float bb = __ldg(B_b);

    const int nbE = gridDim.x - 1 - nbNode;
    const int gw  = b * 8 + (threadIdx.x >> 5);
    const int nw  = nbE * 8;

    for (int e = gw; e < E; e += nw) {
        const int s = __ldg(edges + e);
        const int t = __ldg(edges + E + e);
        float h = __ldg(&g_hs[(size_t)s * 32 + lane])
                + __ldg(&g_ht[(size_t)t * 32 + lane]);
        const float4* rep = (const float4*)(tre + (size_t)e * 32);
        const float4* trp = (const float4*)(ttr + (size_t)e * 32);
        float a0 = 0.f, a1 = 0.f;
#pragma unroll
        for (int c = 0; c < 8; ++c) {
            float4 x = __ldg(rep + c);
            float4 y = __ldg(trp + c);
            a0 = fmaf(x.x, are[4*c+0], a0); a1 = fmaf(x.y, are[4*c+1], a1);
            a0 = fmaf(x.z, are[4*c+2], a0); a1 = fmaf(x.w, are[4*c+3], a1);
            a0 = fmaf(y.x, atr[4*c+0], a0); a1 = fmaf(y.y, atr[4*c+1], a1);
            a0 = fmaf(y.z, atr[4*c+2], a0); a1 = fmaf(y.w, atr[4*c+3], a1);
        }
        h = fmaxf(h + a0 + a1, 0.f);
        float p = h * bw;
#pragma unroll
        for (int o = 16; o; o >>= 1)
            p += __shfl_xor_sync(0xffffffffu, p, o);
        if (lane == 0)
            g_att[e] = 1.f / (1.f + __expf(-(p + bb)));
    }
}

// ---- scatter: block-aggregated counting sort ---------------------------------
__global__ void __launch_bounds__(256)
k_scatter(const int* __restrict__ rels, int E)
{
    __shared__ int h[RMAX];
    __shared__ int cur[RMAX];
    for (int i = threadIdx.x; i < RMAX; i += 256) h[i] = 0;
    __syncthreads();

    const int base = blockIdx.x * 4096;
    int er[16], rr[16];
#pragma unroll
    for (int k = 0; k < 16; ++k) {
        int e = base + k * 256 + threadIdx.x;
        er[k] = e;
        rr[k] = (e < E) ? __ldg(rels + e) : -1;
        if (rr[k] >= 0) atomicAdd(&h[rr[k]], 1);
    }
    __syncthreads();
    for (int i = threadIdx.x; i < RMAX; i += 256) {
        int v = h[i];
        cur[i] = v ? atomicAdd(&g_cur[i], v) : 0;
    }
    __syncthreads();
#pragma unroll
    for (int k = 0; k < 16; ++k) {
        if (rr[k] >= 0) {
            int pos = atomicAdd(&cur[rr[k]], 1);
            g_perm[pos] = er[k];
        }
    }
}

// ---- main: per-relation message + scatter-add ---------------------------------
__global__ void __launch_bounds__(256)
k_main(const float* __restrict__ node_feat,
       const int*   __restrict__ edges,
       float*       __restrict__ out,
       int E)
{
    const int r     = blockIdx.x;
    const int start = __ldg(&g_off[r]);
    const int end   = __ldg(&g_off[r + 1]);
    if (start >= end) return;

    const int lane = threadIdx.x & 31;
    float rwc[32];                     // column `lane` of rel_w[r]
#pragma unroll
    for (int i = 0; i < 32; ++i)
        rwc[i] = __ldg(&g_relw[r * 1024 + i * 32 + lane]);

    const int w = blockIdx.y * 8 + (threadIdx.x >> 5);
    const int W = gridDim.y * 8;

    for (int i = start + w; i < end; i += W) {
        const int e = __ldg(&g_perm[i]);
        const int s = __ldg(edges + e);
        const int t = __ldg(edges + E + e);
        const float att = __ldg(&g_att[e]);

        const float4* sp = (const float4*)(node_feat + (size_t)s * 32);
        float m0 = 0.f, m1 = 0.f;
#pragma unroll
        for (int c = 0; c < 8; ++c) {
            float4 f = __ldg(sp + c);
            m0 = fmaf(f.x, rwc[4*c+0], m0); m1 = fmaf(f.y, rwc[4*c+1], m1);
            m0 = fmaf(f.z, rwc[4*c+2], m0); m1 = fmaf(f.w, rwc[4*c+3], m1);
        }
        const float v = (m0 + m1) * att;

        // pack groups of 4 lanes and issue one vector reduction from 8 lanes
        const int g = (lane & 7) * 4;
        float v0 = __shfl_sync(0xffffffffu, v, g + 0);
        float v1 = __shfl_sync(0xffffffffu, v, g + 1);
        float v2 = __shfl_sync(0xffffffffu, v, g + 2);
        float v3 = __shfl_sync(0xffffffffu, v, g + 3);
        if (lane < 8) {
            float* p = out + (size_t)t * 32 + lane * 4;
            asm volatile("red.global.add.v4.f32 [%0], {%1, %2, %3, %4};"
                         :: "l"(p), "f"(v0), "f"(v1), "f"(v2), "f"(v3)
                         : "memory");
        }
    }
}

extern "C" void kernel_launch(void* const* d_in, const int* in_sizes, int n_in,
                              void* d_out, int out_size)
{
    const float* node_feat = (const float*)d_in[0];
    const float* ttr       = (const float*)d_in[1];
    const float* tre       = (const float*)d_in[2];
    const float* weight    = (const float*)d_in[3];
    const float* w_comp    = (const float*)d_in[4];
    const float* slw       = (const float*)d_in[5];
    const float* A_w       = (const float*)d_in[6];
    const float* A_b       = (const float*)d_in[7];
    const float* B_w       = (const float*)d_in[8];
    const float* B_b       = (const float*)d_in[9];
    const int*   edges     = (const int*)d_in[10];
    const int*   rels      = (const int*)d_in[11];
    float* out = (float*)d_out;

    const int E  = in_sizes[11];
    const int N  = in_sizes[0] / 32;
    const int NB = in_sizes[3] / 1024;
    const int R  = in_sizes[4] / NB;

    int sms = 148;
    cudaDeviceGetAttribute(&sms, cudaDevAttrMultiProcessorCount, 0);

    const int nbNode = (N + 7) / 8;
    const int nbHist = (E + 4095) / 4096;
    const int nbEdge = sms * 8;

    void* cptr = nullptr;
    cudaGetSymbolAddress(&cptr, g_c);
    cudaMemsetAsync(cptr, 0, sizeof(Counters));

    k_phase1<<<R + nbNode + nbHist, 256>>>(weight, w_comp, node_feat, A_w, A_b,
                                           edges, rels, NB, R, N, E, nbNode);
    k_phase2<<<1 + nbNode + nbEdge, 256>>>(node_feat, slw, ttr, tre, A_w,
                                           B_w, B_b, edges, out, R, N, E, nbNode);
    k_scatter<<<nbHist, 256>>>(rels, E);
    k_main<<<dim3(R, 4), 256>>>(node_feat, edges, out, E);
}

// round 4
// speedup vs baseline: 1.3234x; 1.3234x over previous
#include <cuda_runtime.h>
#include <cuda_bf16.h>

// ---------------------------------------------------------------------------
// RGCN layer, 3-launch pipeline (latency-optimized):
//  memset : zero counters
//  k_pre  : basis expansion | node hs/ht | rel+deg histogram + last-block scan
//  k_mid  : out init (deg*(feat@slw)) | counting-sort scatter (sorted src/tgt/eid)
//           | per-edge attention scalar (ILP=2)
//  k_main : per-relation blocks, rel_w col in regs, msg*att, red.v4 (ILP=2)
// ---------------------------------------------------------------------------

#define RMAX 256
#define NMAX 16384
#define EMAX 262144

__device__ float g_relw[RMAX * 1024];
__device__ float g_hs[NMAX * 32];
__device__ float g_ht[NMAX * 32];
__device__ float g_att[EMAX];
__device__ int   g_ssrc[EMAX];
__device__ int   g_stgt[EMAX];
__device__ int   g_seid[EMAX];
__device__ int   g_off[RMAX + 1];
__device__ int   g_cur[RMAX];
struct Counters { int cnt[RMAX]; int deg[NMAX]; int done; };
__device__ Counters g_c;

// ---- launch 1: basis | node hs/ht | histogram (+ last-block scan) -------------
__global__ void __launch_bounds__(256)
k_pre(const float* __restrict__ weight,    // [NB,32,32]
      const float* __restrict__ w_comp,    // [R,NB]
      const float* __restrict__ node_feat, // [N,32]
      const float* __restrict__ A_w,       // [32,128]
      const float* __restrict__ A_b,       // [32]
      const int*   __restrict__ edges,     // [2,E]
      const int*   __restrict__ rels,      // [E]
      int NB, int R, int N, int E, int nbNode, int nbHist)
{
    int b = blockIdx.x;
    const int tid = threadIdx.x;

    if (b < R) {                                    // --- basis expansion ---
        const float* wc = w_comp + b * NB;
        for (int io = tid; io < 1024; io += 256) {
            float acc = 0.f;
            for (int k = 0; k < NB; ++k)
                acc = fmaf(__ldg(wc + k), __ldg(weight + k * 1024 + io), acc);
            g_relw[b * 1024 + io] = acc;
        }
        return;
    }
    b -= R;

    if (b < nbNode) {                               // --- node hs / ht ---
        const int lane = tid & 31;
        const int warp = tid >> 5;
        float aws[32], awt[32];
#pragma unroll
        for (int i = 0; i < 32; ++i) {
            aws[i] = __ldg(A_w + lane * 128 + i);
            awt[i] = __ldg(A_w + lane * 128 + 32 + i);
        }
        const float ab = __ldg(A_b + lane);
#pragma unroll
        for (int k = 0; k < 4; ++k) {
            const int n = b * 32 + warp * 4 + k;
            if (n < N) {
                const float4* fp = (const float4*)(node_feat + (size_t)n * 32);
                float hs = ab, ht = 0.f;
#pragma unroll
                for (int c = 0; c < 8; ++c) {
                    float4 f = __ldg(fp + c);
                    hs = fmaf(f.x, aws[4*c+0], hs); ht = fmaf(f.x, awt[4*c+0], ht);
                    hs = fmaf(f.y, aws[4*c+1], hs); ht = fmaf(f.y, awt[4*c+1], ht);
                    hs = fmaf(f.z, aws[4*c+2], hs); ht = fmaf(f.z, awt[4*c+2], ht);
                    hs = fmaf(f.w, aws[4*c+3], hs); ht = fmaf(f.w, awt[4*c+3], ht);
                }
                g_hs[(size_t)n * 32 + lane] = hs;
                g_ht[(size_t)n * 32 + lane] = ht;
            }
        }
        return;
    }
    b -= nbNode;

    // --- histogram: smem rel counts + global deg counts ---
    __shared__ int sh[RMAX];
    for (int i = tid; i < RMAX; i += 256) sh[i] = 0;
    __syncthreads();
    const int base = b * 4096;
#pragma unroll
    for (int k = 0; k < 16; ++k) {
        const int e = base + k * 256 + tid;
        if (e < E) {
            atomicAdd(&sh[__ldg(rels + e)], 1);
            atomicAdd(&g_c.deg[__ldg(edges + E + e)], 1);
        }
    }
    __syncthreads();
    for (int i = tid; i < RMAX; i += 256) {
        const int v = sh[i];
        if (v) atomicAdd(&g_c.cnt[i], v);
    }
    __threadfence();
    __syncthreads();
    __shared__ int s_last;
    if (tid == 0)
        s_last = (atomicAdd(&g_c.done, 1) == nbHist - 1);
    __syncthreads();
    if (s_last) {                                   // --- last block: scan ---
        __shared__ int buf[RMAX];
        const int c = atomicAdd(&g_c.cnt[tid], 0);  // coherent read
        buf[tid] = c;
        __syncthreads();
#pragma unroll
        for (int d = 1; d < RMAX; d <<= 1) {
            const int v = (tid >= d) ? buf[tid - d] : 0;
            __syncthreads();
            buf[tid] += v;
            __syncthreads();
        }
        if (tid == 0) g_off[0] = 0;
        g_off[tid + 1] = buf[tid];
        g_cur[tid]     = buf[tid] - c;              // exclusive
    }
}

// ---- launch 2: out init | scatter | attention scalars --------------------------
__global__ void __launch_bounds__(256)
k_mid(const float* __restrict__ node_feat,
      const float* __restrict__ slw,   // [32,32]
      const float* __restrict__ ttr,   // [E,32]
      const float* __restrict__ tre,   // [E,32]
      const float* __restrict__ A_w,   // [32,128]
      const float* __restrict__ B_w,   // [32]
      const float* __restrict__ B_b,   // [1]
      const int*   __restrict__ edges, // [2,E]
      const int*   __restrict__ rels,  // [E]
      float*       __restrict__ out,
      int N, int E, int nbNode, int nbHist, int nbEdge)
{
    int b = blockIdx.x;
    const int tid  = threadIdx.x;
    const int lane = tid & 31;
    const int warp = tid >> 5;

    if (b < nbNode) {                               // --- out = deg*(feat@slw) ---
        float slc[32];
#pragma unroll
        for (int i = 0; i < 32; ++i) slc[i] = __ldg(slw + i * 32 + lane);
#pragma unroll
        for (int k = 0; k < 4; ++k) {
            const int n = b * 32 + warp * 4 + k;
            if (n < N) {
                const float4* fp = (const float4*)(node_feat + (size_t)n * 32);
                float s0 = 0.f, s1 = 0.f;
#pragma unroll
                for (int c = 0; c < 8; ++c) {
                    float4 f = __ldg(fp + c);
                    s0 = fmaf(f.x, slc[4*c+0], s0); s1 = fmaf(f.y, slc[4*c+1], s1);
                    s0 = fmaf(f.z, slc[4*c+2], s0); s1 = fmaf(f.w, slc[4*c+3], s1);
                }
                out[(size_t)n * 32 + lane] = (float)__ldg(&g_c.deg[n]) * (s0 + s1);
            }
        }
        return;
    }
    b -= nbNode;

    if (b < nbHist) {                               // --- scatter (sorted arrays) ---
        __shared__ int h[RMAX];
        __shared__ int cur[RMAX];
        for (int i = tid; i < RMAX; i += 256) h[i] = 0;
        __syncthreads();
        const int base = b * 4096;
        int rr[16];
#pragma unroll
        for (int k = 0; k < 16; ++k) {
            const int e = base + k * 256 + tid;
            rr[k] = (e < E) ? __ldg(rels + e) : -1;
            if (rr[k] >= 0) atomicAdd(&h[rr[k]], 1);
        }
        __syncthreads();
        for (int i = tid; i < RMAX; i += 256) {
            const int v = h[i];
            cur[i] = v ? atomicAdd(&g_cur[i], v) : 0;
        }
        __syncthreads();
#pragma unroll
        for (int k = 0; k < 16; ++k) {
            if (rr[k] >= 0) {
                const int e   = base + k * 256 + tid;
                const int pos = atomicAdd(&cur[rr[k]], 1);
                g_ssrc[pos] = __ldg(edges + e);
                g_stgt[pos] = __ldg(edges + E + e);
                g_seid[pos] = e;
            }
        }
        return;
    }
    b -= nbHist;

    // --- attention scalars, ILP = 2 edges per warp-iteration ---
    float are[32], atr[32];
#pragma unroll
    for (int i = 0; i < 32; ++i) {
        are[i] = __ldg(A_w + lane * 128 + 64 + i);
        atr[i] = __ldg(A_w + lane * 128 + 96 + i);
    }
    const float bw = __ldg(B_w + lane);
    const float bb = __ldg(B_b);

    const int gw = b * 8 + warp;
    const int nw = nbEdge * 8;

    for (int e0 = gw * 2; e0 < E; e0 += nw * 2) {
        const int  e1   = e0 + 1;
        const bool has1 = (e1 < E);

        const int s0 = __ldg(edges + e0);
        const int t0 = __ldg(edges + E + e0);
        const int s1 = has1 ? __ldg(edges + e1) : 0;
        const int t1 = has1 ? __ldg(edges + E + e1) : 0;

        float h0 = __ldg(&g_hs[(size_t)s0 * 32 + lane])
                 + __ldg(&g_ht[(size_t)t0 * 32 + lane]);
        float h1 = has1 ? (__ldg(&g_hs[(size_t)s1 * 32 + lane])
                         + __ldg(&g_ht[(size_t)t1 * 32 + lane])) : 0.f;

        const float4* rep0 = (const float4*)(tre + (size_t)e0 * 32);
        const float4* trp0 = (const float4*)(ttr + (size_t)e0 * 32);
        const float4* rep1 = (const float4*)(tre + (size_t)e1 * 32);
        const float4* trp1 = (const float4*)(ttr + (size_t)e1 * 32);

        float a0 = 0.f, a1 = 0.f;
#pragma unroll
        for (int c = 0; c < 8; ++c) {
            float4 x0 = __ldg(rep0 + c);
            float4 y0 = __ldg(trp0 + c);
            float4 x1, y1;
            if (has1) { x1 = __ldg(rep1 + c); y1 = __ldg(trp1 + c); }
            else      { x1 = make_float4(0,0,0,0); y1 = x1; }
            a0 = fmaf(x0.x, are[4*c+0], a0); a1 = fmaf(x1.x, are[4*c+0], a1);
            a0 = fmaf(x0.y, are[4*c+1], a0); a1 = fmaf(x1.y, are[4*c+1], a1);
            a0 = fmaf(x0.z, are[4*c+2], a0); a1 = fmaf(x1.z, are[4*c+2], a1);
            a0 = fmaf(x0.w, are[4*c+3], a0); a1 = fmaf(x1.w, are[4*c+3], a1);
            a0 = fmaf(y0.x, atr[4*c+0], a0); a1 = fmaf(y1.x, atr[4*c+0], a1);
            a0 = fmaf(y0.y, atr[4*c+1], a0); a1 = fmaf(y1.y, atr[4*c+1], a1);
            a0 = fmaf(y0.z, atr[4*c+2], a0); a1 = fmaf(y1.z, atr[4*c+2], a1);
            a0 = fmaf(y0.w, atr[4*c+3], a0); a1 = fmaf(y1.w, atr[4*c+3], a1);
        }
        h0 = fmaxf(h0 + a0, 0.f);
        h1 = fmaxf(h1 + a1, 0.f);

        float p0 = h0 * bw;
        float p1 = h1 * bw;
#pragma unroll
        for (int o = 16; o; o >>= 1) {
            p0 += __shfl_xor_sync(0xffffffffu, p0, o);
            p1 += __shfl_xor_sync(0xffffffffu, p1, o);
        }
        if (lane == 0) {
            g_att[e0] = 1.f / (1.f + __expf(-(p0 + bb)));
            if (has1) g_att[e1] = 1.f / (1.f + __expf(-(p1 + bb)));
        }
    }
}

// ---- launch 3: per-relation message + scatter-add, ILP = 2 --------------------
__global__ void __launch_bounds__(256)
k_main(const float* __restrict__ node_feat,
       float*       __restrict__ out)
{
    const int r     = blockIdx.x;
    const int start = __ldg(&g_off[r]);
    const int end   = __ldg(&g_off[r + 1]);
    if (start >= end) return;

    const int lane = threadIdx.x & 31;
    float rwc[32];                      // column `lane` of rel_w[r]
#pragma unroll
    for (int i = 0; i < 32; ++i)
        rwc[i] = __ldg(&g_relw[r * 1024 + i * 32 + lane]);

    const int w = blockIdx.y * 8 + (threadIdx.x >> 5);
    const int W = gridDim.y * 8;

    for (int i0 = start + w * 2; i0 < end; i0 += W * 2) {
        const int  i1   = i0 + 1;
        const bool has1 = (i1 < end);

        const int s0 = __ldg(&g_ssrc[i0]);
        const int t0 = __ldg(&g_stgt[i0]);
        const float att0 = __ldg(&g_att[__ldg(&g_seid[i0])]);
        const int s1 = has1 ? __ldg(&g_ssrc[i1]) : 0;
        const int t1 = has1 ? __ldg(&g_stgt[i1]) : 0;
        const float att1 = has1 ? __ldg(&g_att[__ldg(&g_seid[i1])]) : 0.f;

        const float4* sp0 = (const float4*)(node_feat + (size_t)s0 * 32);
        const float4* sp1 = (const float4*)(node_feat + (size_t)s1 * 32);

        float m0 = 0.f, m1 = 0.f;
#pragma unroll
        for (int c = 0; c < 8; ++c) {
            float4 f0 = __ldg(sp0 + c);
            float4 f1 = has1 ? __ldg(sp1 + c) : make_float4(0,0,0,0);
            m0 = fmaf(f0.x, rwc[4*c+0], m0); m1 = fmaf(f1.x, rwc[4*c+0], m1);
            m0 = fmaf(f0.y, rwc[4*c+1], m0); m1 = fmaf(f1.y, rwc[4*c+1], m1);
            m0 = fmaf(f0.z, rwc[4*c+2], m0); m1 = fmaf(f1.z, rwc[4*c+2], m1);
            m0 = fmaf(f0.w, rwc[4*c+3], m0); m1 = fmaf(f1.w, rwc[4*c+3], m1);
        }
        const float v0 = m0 * att0;
        const float v1 = m1 * att1;

        // pack 4 lanes/atomic: lanes 0-7 store edge0, lanes 8-15 store edge1
        const int g0 = (lane & 7) * 4;
        float a = __shfl_sync(0xffffffffu, v0, g0 + 0);
        float bq = __shfl_sync(0xffffffffu, v0, g0 + 1);
        float cq = __shfl_sync(0xffffffffu, v0, g0 + 2);
        float dq = __shfl_sync(0xffffffffu, v0, g0 + 3);
        float a2 = __shfl_sync(0xffffffffu, v1, g0 + 0);
        float b2 = __shfl_sync(0xffffffffu, v1, g0 + 1);
        float c2 = __shfl_sync(0xffffffffu, v1, g0 + 2);
        float d2 = __shfl_sync(0xffffffffu, v1, g0 + 3);
        if (lane < 8) {
            float* p = out + (size_t)t0 * 32 + lane * 4;
            asm volatile("red.global.add.v4.f32 [%0], {%1, %2, %3, %4};"
                         :: "l"(p), "f"(a), "f"(bq), "f"(cq), "f"(dq) : "memory");
        } else if (lane < 16 && has1) {
            float* p = out + (size_t)t1 * 32 + (lane - 8) * 4;
            asm volatile("red.global.add.v4.f32 [%0], {%1, %2, %3, %4};"
                         :: "l"(p), "f"(a2), "f"(b2), "f"(c2), "f"(d2) : "memory");
        }
    }
}

extern "C" void kernel_launch(void* const* d_in, const int* in_sizes, int n_in,
                              void* d_out, int out_size)
{
    const float* node_feat = (const float*)d_in[0];
    const float* ttr       = (const float*)d_in[1];
    const float* tre       = (const float*)d_in[2];
    const float* weight    = (const float*)d_in[3];
    const float* w_comp    = (const float*)d_in[4];
    const float* slw       = (const float*)d_in[5];
    const float* A_w       = (const float*)d_in[6];
    const float* A_b       = (const float*)d_in[7];
    const float* B_w       = (const float*)d_in[8];
    const float* B_b       = (const float*)d_in[9];
    const int*   edges     = (const int*)d_in[10];
    const int*   rels      = (const int*)d_in[11];
    float* out = (float*)d_out;

    const int E  = in_sizes[11];
    const int N  = in_sizes[0] / 32;
    const int NB = in_sizes[3] / 1024;
    const int R  = in_sizes[4] / NB;

    int sms = 148;
    cudaDeviceGetAttribute(&sms, cudaDevAttrMultiProcessorCount, 0);

    const int nbNode = (N + 31) / 32;
    const int nbHist = (E + 4095) / 4096;
    const int nbEdge = sms * 4;

    void* cptr = nullptr;
    cudaGetSymbolAddress(&cptr, g_c);
    cudaMemsetAsync(cptr, 0, sizeof(Counters));

    k_pre<<<R + nbNode + nbHist, 256>>>(weight, w_comp, node_feat, A_w, A_b,
                                        edges, rels, NB, R, N, E, nbNode, nbHist);
    k_mid<<<nbNode + nbHist + nbEdge, 256>>>(node_feat, slw, ttr, tre, A_w,
                                             B_w, B_b, edges, rels, out,
                                             N, E, nbNode, nbHist, nbEdge);
    k_main<<<dim3(R, 8), 256>>>(node_feat, out);
}

// round 6
// speedup vs baseline: 1.6601x; 1.2544x over previous
#include <cuda_runtime.h>
#include <cuda_bf16.h>

// ---------------------------------------------------------------------------
// RGCN layer, 3-launch pipeline (latency-optimized):
//  memset : zero counters
//  k_pre  : basis expansion | node hs/ht (A_w smem-staged) | rel+deg histogram
//           + last-block scan
//  k_mid  : out init (deg*(feat@slw)) | counting-sort scatter (sorted src/tgt/eid)
//           | per-edge attention scalar (A_w smem-staged, ILP=2)
//  k_main : per-relation blocks, rel_w col in regs, msg*att, red.v4 (ILP=2)
// ---------------------------------------------------------------------------

#define RMAX 256
#define NMAX 16384
#define EMAX 262144

__device__ float g_relw[RMAX * 1024];
__device__ float g_hs[NMAX * 32];
__device__ float g_ht[NMAX * 32];
__device__ float g_att[EMAX];
__device__ int   g_ssrc[EMAX];
__device__ int   g_stgt[EMAX];
__device__ int   g_seid[EMAX];
__device__ int   g_off[RMAX + 1];
__device__ int   g_cur[RMAX];
struct Counters { int cnt[RMAX]; int deg[NMAX]; int done; };
__device__ Counters g_c;

// ---- launch 1: basis | node hs/ht | histogram (+ last-block scan) -------------
__global__ void __launch_bounds__(256)
k_pre(const float* __restrict__ weight,    // [NB,32,32]
      const float* __restrict__ w_comp,    // [R,NB]
      const float* __restrict__ node_feat, // [N,32]
      const float* __restrict__ A_w,       // [32,128]
      const float* __restrict__ A_b,       // [32]
      const int*   __restrict__ edges,     // [2,E]
      const int*   __restrict__ rels,      // [E]
      int NB, int R, int N, int E, int nbNode, int nbHist)
{
    int b = blockIdx.x;
    const int tid = threadIdx.x;

    if (b < R) {                                    // --- basis expansion ---
        const float* wc = w_comp + b * NB;
        for (int io = tid; io < 1024; io += 256) {
            float acc = 0.f;
            for (int k = 0; k < NB; ++k)
                acc = fmaf(__ldg(wc + k), __ldg(weight + k * 1024 + io), acc);
            g_relw[b * 1024 + io] = acc;
        }
        return;
    }
    b -= R;

    if (b < nbNode) {                               // --- node hs / ht ---
        // stage A_w coalesced into smem (pitch 129 -> conflict-free reads)
        __shared__ float sA[32 * 129];
        for (int idx = tid; idx < 4096; idx += 256)
            sA[(idx >> 7) * 129 + (idx & 127)] = __ldg(A_w + idx);
        __syncthreads();

        const int lane = tid & 31;
        const int warp = tid >> 5;
        float aws[32], awt[32];
#pragma unroll
        for (int i = 0; i < 32; ++i) {
            aws[i] = sA[lane * 129 + i];
            awt[i] = sA[lane * 129 + 32 + i];
        }
        const float ab = __ldg(A_b + lane);
#pragma unroll
        for (int k = 0; k < 4; ++k) {
            const int n = b * 32 + warp * 4 + k;
            if (n < N) {
                const float4* fp = (const float4*)(node_feat + (size_t)n * 32);
                float hs = ab, ht = 0.f;
#pragma unroll
                for (int c = 0; c < 8; ++c) {
                    float4 f = __ldg(fp + c);
                    hs = fmaf(f.x, aws[4*c+0], hs); ht = fmaf(f.x, awt[4*c+0], ht);
                    hs = fmaf(f.y, aws[4*c+1], hs); ht = fmaf(f.y, awt[4*c+1], ht);
                    hs = fmaf(f.z, aws[4*c+2], hs); ht = fmaf(f.z, awt[4*c+2], ht);
                    hs = fmaf(f.w, aws[4*c+3], hs); ht = fmaf(f.w, awt[4*c+3], ht);
                }
                g_hs[(size_t)n * 32 + lane] = hs;
                g_ht[(size_t)n * 32 + lane] = ht;
            }
        }
        return;
    }
    b -= nbNode;

    // --- histogram: smem rel counts + global deg counts ---
    __shared__ int sh[RMAX];
    for (int i = tid; i < RMAX; i += 256) sh[i] = 0;
    __syncthreads();
    const int base = b * 4096;
#pragma unroll
    for (int k = 0; k < 16; ++k) {
        const int e = base + k * 256 + tid;
        if (e < E) {
            atomicAdd(&sh[__ldg(rels + e)], 1);
            atomicAdd(&g_c.deg[__ldg(edges + E + e)], 1);
        }
    }
    __syncthreads();
    for (int i = tid; i < RMAX; i += 256) {
        const int v = sh[i];
        if (v) atomicAdd(&g_c.cnt[i], v);
    }
    __threadfence();
    __syncthreads();
    __shared__ int s_last;
    if (tid == 0)
        s_last = (atomicAdd(&g_c.done, 1) == nbHist - 1);
    __syncthreads();
    if (s_last) {                                   // --- last block: scan ---
        __shared__ int buf[RMAX];
        const int c = atomicAdd(&g_c.cnt[tid], 0);  // coherent read
        buf[tid] = c;
        __syncthreads();
#pragma unroll
        for (int d = 1; d < RMAX; d <<= 1) {
            const int v = (tid >= d) ? buf[tid - d] : 0;
            __syncthreads();
            buf[tid] += v;
            __syncthreads();
        }
        if (tid == 0) g_off[0] = 0;
        g_off[tid + 1] = buf[tid];
        g_cur[tid]     = buf[tid] - c;              // exclusive
    }
}

// ---- launch 2: out init | scatter | attention scalars --------------------------
__global__ void __launch_bounds__(256)
k_mid(const float* __restrict__ node_feat,
      const float* __restrict__ slw,   // [32,32]
      const float* __restrict__ ttr,   // [E,32]
      const float* __restrict__ tre,   // [E,32]
      const float* __restrict__ A_w,   // [32,128]
      const float* __restrict__ B_w,   // [32]
      const float* __restrict__ B_b,   // [1]
      const int*   __restrict__ edges, // [2,E]
      const int*   __restrict__ rels,  // [E]
      float*       __restrict__ out,
      int N, int E, int nbNode, int nbHist, int nbEdge)
{
    int b = blockIdx.x;
    const int tid  = threadIdx.x;
    const int lane = tid & 31;
    const int warp = tid >> 5;

    if (b < nbNode) {                               // --- out = deg*(feat@slw) ---
        float slc[32];
#pragma unroll
        for (int i = 0; i < 32; ++i) slc[i] = __ldg(slw + i * 32 + lane);
#pragma unroll
        for (int k = 0; k < 4; ++k) {
            const int n = b * 32 + warp * 4 + k;
            if (n < N) {
                const float4* fp = (const float4*)(node_feat + (size_t)n * 32);
                float s0 = 0.f, s1 = 0.f;
#pragma unroll
                for (int c = 0; c < 8; ++c) {
                    float4 f = __ldg(fp + c);
                    s0 = fmaf(f.x, slc[4*c+0], s0); s1 = fmaf(f.y, slc[4*c+1], s1);
                    s0 = fmaf(f.z, slc[4*c+2], s0); s1 = fmaf(f.w, slc[4*c+3], s1);
                }
                out[(size_t)n * 32 + lane] = (float)__ldg(&g_c.deg[n]) * (s0 + s1);
            }
        }
        return;
    }
    b -= nbNode;

    if (b < nbHist) {                               // --- scatter (sorted arrays) ---
        __shared__ int h[RMAX];
        __shared__ int cur[RMAX];
        for (int i = tid; i < RMAX; i += 256) h[i] = 0;
        __syncthreads();
        const int base = b * 4096;
        int rr[16];
#pragma unroll
        for (int k = 0; k < 16; ++k) {
            const int e = base + k * 256 + tid;
            rr[k] = (e < E) ? __ldg(rels + e) : -1;
            if (rr[k] >= 0) atomicAdd(&h[rr[k]], 1);
        }
        __syncthreads();
        for (int i = tid; i < RMAX; i += 256) {
            const int v = h[i];
            cur[i] = v ? atomicAdd(&g_cur[i], v) : 0;
        }
        __syncthreads();
#pragma unroll
        for (int k = 0; k < 16; ++k) {
            if (rr[k] >= 0) {
                const int e   = base + k * 256 + tid;
                const int pos = atomicAdd(&cur[rr[k]], 1);
                g_ssrc[pos] = __ldg(edges + e);
                g_stgt[pos] = __ldg(edges + E + e);
                g_seid[pos] = e;
            }
        }
        return;
    }
    b -= nbHist;

    // --- attention scalars, A_w smem-staged, ILP = 2 ---
    __shared__ float sA[32 * 129];
    for (int idx = tid; idx < 4096; idx += 256)
        sA[(idx >> 7) * 129 + (idx & 127)] = __ldg(A_w + idx);
    __syncthreads();

    float are[32], atr[32];
#pragma unroll
    for (int i = 0; i < 32; ++i) {
        are[i] = sA[lane * 129 + 64 + i];
        atr[i] = sA[lane * 129 + 96 + i];
    }
    const float bw = __ldg(B_w + lane);
    const float bb = __ldg(B_b);

    const int gw = b * 8 + warp;
    const int nw = nbEdge * 8;

    for (int e0 = gw * 2; e0 < E; e0 += nw * 2) {
        const int  e1   = e0 + 1;
        const bool has1 = (e1 < E);

        const int s0 = __ldg(edges + e0);
        const int t0 = __ldg(edges + E + e0);
        const int s1 = has1 ? __ldg(edges + e1) : 0;
        const int t1 = has1 ? __ldg(edges + E + e1) : 0;

        float h0 = __ldg(&g_hs[(size_t)s0 * 32 + lane])
                 + __ldg(&g_ht[(size_t)t0 * 32 + lane]);
        float h1 = has1 ? (__ldg(&g_hs[(size_t)s1 * 32 + lane])
                         + __ldg(&g_ht[(size_t)t1 * 32 + lane])) : 0.f;

        const float4* rep0 = (const float4*)(tre + (size_t)e0 * 32);
        const float4* trp0 = (const float4*)(ttr + (size_t)e0 * 32);
        const float4* rep1 = (const float4*)(tre + (size_t)e1 * 32);
        const float4* trp1 = (const float4*)(ttr + (size_t)e1 * 32);

        float a0 = 0.f, a1 = 0.f;
#pragma unroll
        for (int c = 0; c < 8; ++c) {
            float4 x0 = __ldg(rep0 + c);
            float4 y0 = __ldg(trp0 + c);
            float4 x1, y1;
            if (has1) { x1 = __ldg(rep1 + c); y1 = __ldg(trp1 + c); }
            else      { x1 = make_float4(0,0,0,0); y1 = x1; }
            a0 = fmaf(x0.x, are[4*c+0], a0); a1 = fmaf(x1.x, are[4*c+0], a1);
            a0 = fmaf(x0.y, are[4*c+1], a0); a1 = fmaf(x1.y, are[4*c+1], a1);
            a0 = fmaf(x0.z, are[4*c+2], a0); a1 = fmaf(x1.z, are[4*c+2], a1);
            a0 = fmaf(x0.w, are[4*c+3], a0); a1 = fmaf(x1.w, are[4*c+3], a1);
            a0 = fmaf(y0.x, atr[4*c+0], a0); a1 = fmaf(y1.x, atr[4*c+0], a1);
            a0 = fmaf(y0.y, atr[4*c+1], a0); a1 = fmaf(y1.y, atr[4*c+1], a1);
            a0 = fmaf(y0.z, atr[4*c+2], a0); a1 = fmaf(y1.z, atr[4*c+2], a1);
            a0 = fmaf(y0.w, atr[4*c+3], a0); a1 = fmaf(y1.w, atr[4*c+3], a1);
        }
        h0 = fmaxf(h0 + a0, 0.f);
        h1 = fmaxf(h1 + a1, 0.f);

        float p0 = h0 * bw;
        float p1 = h1 * bw;
#pragma unroll
        for (int o = 16; o; o >>= 1) {
            p0 += __shfl_xor_sync(0xffffffffu, p0, o);
            p1 += __shfl_xor_sync(0xffffffffu, p1, o);
        }
        if (lane == 0) {
            g_att[e0] = 1.f / (1.f + __expf(-(p0 + bb)));
            if (has1) g_att[e1] = 1.f / (1.f + __expf(-(p1 + bb)));
        }
    }
}

// ---- launch 3: per-relation message + scatter-add, ILP = 2 --------------------
__global__ void __launch_bounds__(256)
k_main(const float* __restrict__ node_feat,
       float*       __restrict__ out)
{
    const int r     = blockIdx.x;
    const int start = __ldg(&g_off[r]);
    const int end   = __ldg(&g_off[r + 1]);
    if (start >= end) return;

    const int lane = threadIdx.x & 31;
    float rwc[32];                      // column `lane` of rel_w[r]
#pragma unroll
    for (int i = 0; i < 32; ++i)
        rwc[i] = __ldg(&g_relw[r * 1024 + i * 32 + lane]);

    const int w = blockIdx.y * 8 + (threadIdx.x >> 5);
    const int W = gridDim.y * 8;

    for (int i0 = start + w * 2; i0 < end; i0 += W * 2) {
        const int  i1   = i0 + 1;
        const bool has1 = (i1 < end);

        const int s0 = __ldg(&g_ssrc[i0]);
        const int t0 = __ldg(&g_stgt[i0]);
        const float att0 = __ldg(&g_att[__ldg(&g_seid[i0])]);
        const int s1 = has1 ? __ldg(&g_ssrc[i1]) : 0;
        const int t1 = has1 ? __ldg(&g_stgt[i1]) : 0;
        const float att1 = has1 ? __ldg(&g_att[__ldg(&g_seid[i1])]) : 0.f;

        const float4* sp0 = (const float4*)(node_feat + (size_t)s0 * 32);
        const float4* sp1 = (const float4*)(node_feat + (size_t)s1 * 32);

        float m0 = 0.f, m1 = 0.f;
#pragma unroll
        for (int c = 0; c < 8; ++c) {
            float4 f0 = __ldg(sp0 + c);
            float4 f1 = has1 ? __ldg(sp1 + c) : make_float4(0,0,0,0);
            m0 = fmaf(f0.x, rwc[4*c+0], m0); m1 = fmaf(f1.x, rwc[4*c+0], m1);
            m0 = fmaf(f0.y, rwc[4*c+1], m0); m1 = fmaf(f1.y, rwc[4*c+1], m1);
            m0 = fmaf(f0.z, rwc[4*c+2], m0); m1 = fmaf(f1.z, rwc[4*c+2], m1);
            m0 = fmaf(f0.w, rwc[4*c+3], m0); m1 = fmaf(f1.w, rwc[4*c+3], m1);
        }
        const float v0 = m0 * att0;
        const float v1 = m1 * att1;

        // pack 4 lanes/atomic: lanes 0-7 store edge0, lanes 8-15 store edge1
        const int g0 = (lane & 7) * 4;
        float a  = __shfl_sync(0xffffffffu, v0, g0 + 0);
        float bq = __shfl_sync(0xffffffffu, v0, g0 + 1);
        float cq = __shfl_sync(0xffffffffu, v0, g0 + 2);
        float dq = __shfl_sync(0xffffffffu, v0, g0 + 3);
        float a2 = __shfl_sync(0xffffffffu, v1, g0 + 0);
        float b2 = __shfl_sync(0xffffffffu, v1, g0 + 1);
        float c2 = __shfl_sync(0xffffffffu, v1, g0 + 2);
        float d2 = __shfl_sync(0xffffffffu, v1, g0 + 3);
        if (lane < 8) {
            float* p = out + (size_t)t0 * 32 + lane * 4;
            asm volatile("red.global.add.v4.f32 [%0], {%1, %2, %3, %4};"
                         :: "l"(p), "f"(a), "f"(bq), "f"(cq), "f"(dq) : "memory");
        } else if (lane < 16 && has1) {
            float* p = out + (size_t)t1 * 32 + (lane - 8) * 4;
            asm volatile("red.global.add.v4.f32 [%0], {%1, %2, %3, %4};"
                         :: "l"(p), "f"(a2), "f"(b2), "f"(c2), "f"(d2) : "memory");
        }
    }
}

extern "C" void kernel_launch(void* const* d_in, const int* in_sizes, int n_in,
                              void* d_out, int out_size)
{
    const float* node_feat = (const float*)d_in[0];
    const float* ttr       = (const float*)d_in[1];
    const float* tre       = (const float*)d_in[2];
    const float* weight    = (const float*)d_in[3];
    const float* w_comp    = (const float*)d_in[4];
    const float* slw       = (const float*)d_in[5];
    const float* A_w       = (const float*)d_in[6];
    const float* A_b       = (const float*)d_in[7];
    const float* B_w       = (const float*)d_in[8];
    const float* B_b       = (const float*)d_in[9];
    const int*   edges     = (const int*)d_in[10];
    const int*   rels      = (const int*)d_in[11];
    float* out = (float*)d_out;

    const int E  = in_sizes[11];
    const int N  = in_sizes[0] / 32;
    const int NB = in_sizes[3] / 1024;
    const int R  = in_sizes[4] / NB;

    int sms = 148;
    cudaDeviceGetAttribute(&sms, cudaDevAttrMultiProcessorCount, 0);

    const int nbNode = (N + 31) / 32;
    const int nbHist = (E + 4095) / 4096;
    const int nbEdge = sms * 4;

    void* cptr = nullptr;
    cudaGetSymbolAddress(&cptr, g_c);
    cudaMemsetAsync(cptr, 0, sizeof(Counters));

    k_pre<<<R + nbNode + nbHist, 256>>>(weight, w_comp, node_feat, A_w, A_b,
                                        edges, rels, NB, R, N, E, nbNode, nbHist);
    k_mid<<<nbNode + nbHist + nbEdge, 256>>>(node_feat, slw, ttr, tre, A_w,
                                             B_w, B_b, edges, rels, out,
                                             N, E, nbNode, nbHist, nbEdge);
    k_main<<<dim3(R, 8), 256>>>(node_feat, out);
}

// round 7
// speedup vs baseline: 2.1903x; 1.3194x over previous
#include <cuda_runtime.h>
#include <cuda_bf16.h>

// ---------------------------------------------------------------------------
// RGCN layer, 3-launch pipeline (latency-optimized):
//  memset : zero counters
//  k_pre  : basis expansion | node hs/ht (A_w smem-staged) | rel+deg histogram
//           + last-block scan
//  k_mid  : out init (deg*(feat@slw)) | counting-sort scatter (sorted src/tgt/eid)
//           | per-edge attention scalar (f32x2 FMA, ILP=4, clamped indices)
//  k_main : per-relation blocks, rel_w col packed f32x2, msg*att, red.v4 (ILP=2)
// ---------------------------------------------------------------------------

#define RMAX 256
#define NMAX 16384
#define EMAX 262144

typedef unsigned long long u64;

__device__ __forceinline__ u64 pk2(float lo, float hi) {
    u64 r; asm("mov.b64 %0, {%1, %2};" : "=l"(r) : "f"(lo), "f"(hi)); return r;
}
__device__ __forceinline__ void fma2(u64& d, u64 a, u64 b) {
    asm("fma.rn.f32x2 %0, %1, %2, %0;" : "+l"(d) : "l"(a), "l"(b));
}
__device__ __forceinline__ float upk_sum(u64 v) {
    float lo, hi; asm("mov.b64 {%0, %1}, %2;" : "=f"(lo), "=f"(hi) : "l"(v));
    return lo + hi;
}

__device__ float g_relw[RMAX * 1024];
__device__ float g_hs[NMAX * 32];
__device__ float g_ht[NMAX * 32];
__device__ float g_att[EMAX];
__device__ int   g_ssrc[EMAX];
__device__ int   g_stgt[EMAX];
__device__ int   g_seid[EMAX];
__device__ int   g_off[RMAX + 1];
__device__ int   g_cur[RMAX];
struct Counters { int cnt[RMAX]; int deg[NMAX]; int done; };
__device__ Counters g_c;

// ---- launch 1: basis | node hs/ht | histogram (+ last-block scan) -------------
__global__ void __launch_bounds__(256)
k_pre(const float* __restrict__ weight,    // [NB,32,32]
      const float* __restrict__ w_comp,    // [R,NB]
      const float* __restrict__ node_feat, // [N,32]
      const float* __restrict__ A_w,       // [32,128]
      const float* __restrict__ A_b,       // [32]
      const int*   __restrict__ edges,     // [2,E]
      const int*   __restrict__ rels,      // [E]
      int NB, int R, int N, int E, int nbNode, int nbHist)
{
    int b = blockIdx.x;
    const int tid = threadIdx.x;

    if (b < R) {                                    // --- basis expansion ---
        const float* wc = w_comp + b * NB;
        for (int io = tid; io < 1024; io += 256) {
            float acc = 0.f;
            for (int k = 0; k < NB; ++k)
                acc = fmaf(__ldg(wc + k), __ldg(weight + k * 1024 + io), acc);
            g_relw[b * 1024 + io] = acc;
        }
        return;
    }
    b -= R;

    if (b < nbNode) {                               // --- node hs / ht ---
        __shared__ float sA[32 * 129];
        for (int idx = tid; idx < 4096; idx += 256)
            sA[(idx >> 7) * 129 + (idx & 127)] = __ldg(A_w + idx);
        __syncthreads();

        const int lane = tid & 31;
        const int warp = tid >> 5;
        float aws[32], awt[32];
#pragma unroll
        for (int i = 0; i < 32; ++i) {
            aws[i] = sA[lane * 129 + i];
            awt[i] = sA[lane * 129 + 32 + i];
        }
        const float ab = __ldg(A_b + lane);
#pragma unroll
        for (int k = 0; k < 4; ++k) {
            const int n = b * 32 + warp * 4 + k;
            if (n < N) {
                const float4* fp = (const float4*)(node_feat + (size_t)n * 32);
                float hs = ab, ht = 0.f;
#pragma unroll
                for (int c = 0; c < 8; ++c) {
                    float4 f = __ldg(fp + c);
                    hs = fmaf(f.x, aws[4*c+0], hs); ht = fmaf(f.x, awt[4*c+0], ht);
                    hs = fmaf(f.y, aws[4*c+1], hs); ht = fmaf(f.y, awt[4*c+1], ht);
                    hs = fmaf(f.z, aws[4*c+2], hs); ht = fmaf(f.z, awt[4*c+2], ht);
                    hs = fmaf(f.w, aws[4*c+3], hs); ht = fmaf(f.w, awt[4*c+3], ht);
                }
                g_hs[(size_t)n * 32 + lane] = hs;
                g_ht[(size_t)n * 32 + lane] = ht;
            }
        }
        return;
    }
    b -= nbNode;

    // --- histogram: smem rel counts + global deg counts ---
    __shared__ int sh[RMAX];
    for (int i = tid; i < RMAX; i += 256) sh[i] = 0;
    __syncthreads();
    const int base = b * 4096;
#pragma unroll
    for (int k = 0; k < 16; ++k) {
        const int e = base + k * 256 + tid;
        if (e < E) {
            atomicAdd(&sh[__ldg(rels + e)], 1);
            atomicAdd(&g_c.deg[__ldg(edges + E + e)], 1);
        }
    }
    __syncthreads();
    for (int i = tid; i < RMAX; i += 256) {
        const int v = sh[i];
        if (v) atomicAdd(&g_c.cnt[i], v);
    }
    __threadfence();
    __syncthreads();
    __shared__ int s_last;
    if (tid == 0)
        s_last = (atomicAdd(&g_c.done, 1) == nbHist - 1);
    __syncthreads();
    if (s_last) {                                   // --- last block: scan ---
        __shared__ int buf[RMAX];
        const int c = atomicAdd(&g_c.cnt[tid], 0);  // coherent read
        buf[tid] = c;
        __syncthreads();
#pragma unroll
        for (int d = 1; d < RMAX; d <<= 1) {
            const int v = (tid >= d) ? buf[tid - d] : 0;
            __syncthreads();
            buf[tid] += v;
            __syncthreads();
        }
        if (tid == 0) g_off[0] = 0;
        g_off[tid + 1] = buf[tid];
        g_cur[tid]     = buf[tid] - c;              // exclusive
    }
}

// ---- launch 2: out init | scatter | attention scalars --------------------------
__global__ void __launch_bounds__(256)
k_mid(const float* __restrict__ node_feat,
      const float* __restrict__ slw,   // [32,32]
      const float* __restrict__ ttr,   // [E,32]
      const float* __restrict__ tre,   // [E,32]
      const float* __restrict__ A_w,   // [32,128]
      const float* __restrict__ B_w,   // [32]
      const float* __restrict__ B_b,   // [1]
      const int*   __restrict__ edges, // [2,E]
      const int*   __restrict__ rels,  // [E]
      float*       __restrict__ out,
      int N, int E, int nbNode, int nbHist, int nbEdge)
{
    int b = blockIdx.x;
    const int tid  = threadIdx.x;
    const int lane = tid & 31;
    const int warp = tid >> 5;

    if (b < nbNode) {                               // --- out = deg*(feat@slw) ---
        float slc[32];
#pragma unroll
        for (int i = 0; i < 32; ++i) slc[i] = __ldg(slw + i * 32 + lane);
#pragma unroll
        for (int k = 0; k < 4; ++k) {
            const int n = b * 32 + warp * 4 + k;
            if (n < N) {
                const float4* fp = (const float4*)(node_feat + (size_t)n * 32);
                float s0 = 0.f, s1 = 0.f;
#pragma unroll
                for (int c = 0; c < 8; ++c) {
                    float4 f = __ldg(fp + c);
                    s0 = fmaf(f.x, slc[4*c+0], s0); s1 = fmaf(f.y, slc[4*c+1], s1);
                    s0 = fmaf(f.z, slc[4*c+2], s0); s1 = fmaf(f.w, slc[4*c+3], s1);
                }
                out[(size_t)n * 32 + lane] = (float)__ldg(&g_c.deg[n]) * (s0 + s1);
            }
        }
        return;
    }
    b -= nbNode;

    if (b < nbHist) {                               // --- scatter (sorted arrays) ---
        __shared__ int h[RMAX];
        __shared__ int cur[RMAX];
        for (int i = tid; i < RMAX; i += 256) h[i] = 0;
        __syncthreads();
        const int base = b * 4096;
        int rr[16];
#pragma unroll
        for (int k = 0; k < 16; ++k) {
            const int e = base + k * 256 + tid;
            rr[k] = (e < E) ? __ldg(rels + e) : -1;
            if (rr[k] >= 0) atomicAdd(&h[rr[k]], 1);
        }
        __syncthreads();
        for (int i = tid; i < RMAX; i += 256) {
            const int v = h[i];
            cur[i] = v ? atomicAdd(&g_cur[i], v) : 0;
        }
        __syncthreads();
#pragma unroll
        for (int k = 0; k < 16; ++k) {
            if (rr[k] >= 0) {
                const int e   = base + k * 256 + tid;
                const int pos = atomicAdd(&cur[rr[k]], 1);
                g_ssrc[pos] = __ldg(edges + e);
                g_stgt[pos] = __ldg(edges + E + e);
                g_seid[pos] = e;
            }
        }
        return;
    }
    b -= nbHist;

    // --- attention scalars: A_w smem-staged, f32x2 FMA, ILP = 4 (clamped) ---
    __shared__ float sA[32 * 129];
    for (int idx = tid; idx < 4096; idx += 256)
        sA[(idx >> 7) * 129 + (idx & 127)] = __ldg(A_w + idx);
    __syncthreads();

    u64 areP[16], atrP[16];
#pragma unroll
    for (int i = 0; i < 16; ++i) {
        areP[i] = pk2(sA[lane * 129 + 64 + 2*i], sA[lane * 129 + 64 + 2*i + 1]);
        atrP[i] = pk2(sA[lane * 129 + 96 + 2*i], sA[lane * 129 + 96 + 2*i + 1]);
    }
    const float bw = __ldg(B_w + lane);
    const float bb = __ldg(B_b);

    const int gw = b * 8 + warp;
    const int nw = nbEdge * 8;

    for (int e0 = gw * 4; e0 < E; e0 += nw * 4) {
        int ea[4], ss[4], tt[4];
#pragma unroll
        for (int k = 0; k < 4; ++k) {
            ea[k] = min(e0 + k, E - 1);             // always in-bounds
            ss[k] = __ldg(edges + ea[k]);
            tt[k] = __ldg(edges + E + ea[k]);
        }
        float hh[4];
#pragma unroll
        for (int k = 0; k < 4; ++k)
            hh[k] = __ldg(&g_hs[(size_t)ss[k] * 32 + lane])
                  + __ldg(&g_ht[(size_t)tt[k] * 32 + lane]);

        u64 acc[4] = {0ull, 0ull, 0ull, 0ull};
#pragma unroll
        for (int c = 0; c < 8; ++c) {
#pragma unroll
            for (int k = 0; k < 4; ++k) {
                ulonglong2 X = __ldg((const ulonglong2*)(tre + (size_t)ea[k] * 32) + c);
                ulonglong2 Y = __ldg((const ulonglong2*)(ttr + (size_t)ea[k] * 32) + c);
                fma2(acc[k], X.x, areP[2*c]);  fma2(acc[k], X.y, areP[2*c+1]);
                fma2(acc[k], Y.x, atrP[2*c]);  fma2(acc[k], Y.y, atrP[2*c+1]);
            }
        }
        float p[4];
#pragma unroll
        for (int k = 0; k < 4; ++k)
            p[k] = fmaxf(hh[k] + upk_sum(acc[k]), 0.f) * bw;
#pragma unroll
        for (int o = 16; o; o >>= 1) {
#pragma unroll
            for (int k = 0; k < 4; ++k)
                p[k] += __shfl_xor_sync(0xffffffffu, p[k], o);
        }
        if (lane == 0) {
#pragma unroll
            for (int k = 0; k < 4; ++k)
                if (e0 + k < E)
                    g_att[ea[k]] = 1.f / (1.f + __expf(-(p[k] + bb)));
        }
    }
}

// ---- launch 3: per-relation message + scatter-add, f32x2, ILP = 2 --------------
__global__ void __launch_bounds__(256)
k_main(const float* __restrict__ node_feat,
       float*       __restrict__ out)
{
    const int r     = blockIdx.x;
    const int start = __ldg(&g_off[r]);
    const int end   = __ldg(&g_off[r + 1]);
    if (start >= end) return;

    const int lane = threadIdx.x & 31;
    u64 rwcP[16];                       // column `lane` of rel_w[r], packed pairs
#pragma unroll
    for (int i = 0; i < 16; ++i)
        rwcP[i] = pk2(__ldg(&g_relw[r * 1024 + (2*i)   * 32 + lane]),
                      __ldg(&g_relw[r * 1024 + (2*i+1) * 32 + lane]));

    const int w = blockIdx.y * 8 + (threadIdx.x >> 5);
    const int W = gridDim.y * 8;

    for (int i0 = start + w * 2; i0 < end; i0 += W * 2) {
        const int  i1   = i0 + 1;
        const bool has1 = (i1 < end);

        const int s0 = __ldg(&g_ssrc[i0]);
        const int t0 = __ldg(&g_stgt[i0]);
        const float att0 = __ldg(&g_att[__ldg(&g_seid[i0])]);
        const int s1 = has1 ? __ldg(&g_ssrc[i1]) : 0;
        const int t1 = has1 ? __ldg(&g_stgt[i1]) : 0;
        const float att1 = has1 ? __ldg(&g_att[__ldg(&g_seid[i1])]) : 0.f;

        const ulonglong2* sp0 = (const ulonglong2*)(node_feat + (size_t)s0 * 32);
        const ulonglong2* sp1 = (const ulonglong2*)(node_feat + (size_t)s1 * 32);

        u64 acc0 = 0ull, acc1 = 0ull;
#pragma unroll
        for (int c = 0; c < 8; ++c) {
            ulonglong2 F0 = __ldg(sp0 + c);
            ulonglong2 F1 = __ldg(sp1 + c);
            fma2(acc0, F0.x, rwcP[2*c]); fma2(acc0, F0.y, rwcP[2*c+1]);
            fma2(acc1, F1.x, rwcP[2*c]); fma2(acc1, F1.y, rwcP[2*c+1]);
        }
        const float v0 = upk_sum(acc0) * att0;
        const float v1 = upk_sum(acc1) * att1;

        // pack 4 lanes/atomic: lanes 0-7 store edge0, lanes 8-15 store edge1
        const int g0 = (lane & 7) * 4;
        float a  = __shfl_sync(0xffffffffu, v0, g0 + 0);
        float bq = __shfl_sync(0xffffffffu, v0, g0 + 1);
        float cq = __shfl_sync(0xffffffffu, v0, g0 + 2);
        float dq = __shfl_sync(0xffffffffu, v0, g0 + 3);
        float a2 = __shfl_sync(0xffffffffu, v1, g0 + 0);
        float b2 = __shfl_sync(0xffffffffu, v1, g0 + 1);
        float c2 = __shfl_sync(0xffffffffu, v1, g0 + 2);
        float d2 = __shfl_sync(0xffffffffu, v1, g0 + 3);
        if (lane < 8) {
            float* p = out + (size_t)t0 * 32 + lane * 4;
            asm volatile("red.global.add.v4.f32 [%0], {%1, %2, %3, %4};"
                         :: "l"(p), "f"(a), "f"(bq), "f"(cq), "f"(dq) : "memory");
        } else if (lane < 16 && has1) {
            float* p = out + (size_t)t1 * 32 + (lane - 8) * 4;
            asm volatile("red.global.add.v4.f32 [%0], {%1, %2, %3, %4};"
                         :: "l"(p), "f"(a2), "f"(b2), "f"(c2), "f"(d2) : "memory");
        }
    }
}

extern "C" void kernel_launch(void* const* d_in, const int* in_sizes, int n_in,
                              void* d_out, int out_size)
{
    const float* node_feat = (const float*)d_in[0];
    const float* ttr       = (const float*)d_in[1];
    const float* tre       = (const float*)d_in[2];
    const float* weight    = (const float*)d_in[3];
    const float* w_comp    = (const float*)d_in[4];
    const float* slw       = (const float*)d_in[5];
    const float* A_w       = (const float*)d_in[6];
    const float* A_b       = (const float*)d_in[7];
    const float* B_w       = (const float*)d_in[8];
    const float* B_b       = (const float*)d_in[9];
    const int*   edges     = (const int*)d_in[10];
    const int*   rels      = (const int*)d_in[11];
    float* out = (float*)d_out;

    const int E  = in_sizes[11];
    const int N  = in_sizes[0] / 32;
    const int NB = in_sizes[3] / 1024;
    const int R  = in_sizes[4] / NB;

    int sms = 148;
    cudaDeviceGetAttribute(&sms, cudaDevAttrMultiProcessorCount, 0);

    const int nbNode = (N + 31) / 32;
    const int nbHist = (E + 4095) / 4096;
    const int nbEdge = sms * 4;

    void* cptr = nullptr;
    cudaGetSymbolAddress(&cptr, g_c);
    cudaMemsetAsync(cptr, 0, sizeof(Counters));

    k_pre<<<R + nbNode + nbHist, 256>>>(weight, w_comp, node_feat, A_w, A_b,
                                        edges, rels, NB, R, N, E, nbNode, nbHist);
    k_mid<<<nbNode + nbHist + nbEdge, 256>>>(node_feat, slw, ttr, tre, A_w,
                                             B_w, B_b, edges, rels, out,
                                             N, E, nbNode, nbHist, nbEdge);
    k_main<<<dim3(R, 8), 256>>>(node_feat, out);
}

// round 8
// speedup vs baseline: 2.3336x; 1.0654x over previous
#include <cuda_runtime.h>
#include <cuda_bf16.h>

// ---------------------------------------------------------------------------
// RGCN layer, 3-launch pipeline (latency-optimized):
//  memset : zero counters
//  k_pre  : basis expansion | node hs/ht (A_w smem-staged, f32x2 packed)
//           | rel+deg histogram + last-block scan
//  k_mid  : out init (deg*(feat@slw)) | counting-sort scatter
//           | per-edge attention scalar (f32x2 FMA, ILP=4, clamped indices)
//  k_main : per-relation blocks, rel_w f32x2, ILP=4, full-warp red.v4
// ---------------------------------------------------------------------------

#define RMAX 256
#define NMAX 16384
#define EMAX 262144

typedef unsigned long long u64;

__device__ __forceinline__ u64 pk2(float lo, float hi) {
    u64 r; asm("mov.b64 %0, {%1, %2};" : "=l"(r) : "f"(lo), "f"(hi)); return r;
}
__device__ __forceinline__ void fma2(u64& d, u64 a, u64 b) {
    asm("fma.rn.f32x2 %0, %1, %2, %0;" : "+l"(d) : "l"(a), "l"(b));
}
__device__ __forceinline__ float upk_sum(u64 v) {
    float lo, hi; asm("mov.b64 {%0, %1}, %2;" : "=f"(lo), "=f"(hi) : "l"(v));
    return lo + hi;
}
__device__ __forceinline__ void upk(u64 v, float& lo, float& hi) {
    asm("mov.b64 {%0, %1}, %2;" : "=f"(lo), "=f"(hi) : "l"(v));
}

__device__ float g_relw[RMAX * 1024];
__device__ float g_hs[NMAX * 32];
__device__ float g_ht[NMAX * 32];
__device__ float g_att[EMAX];
__device__ int   g_ssrc[EMAX];
__device__ int   g_stgt[EMAX];
__device__ int   g_seid[EMAX];
__device__ int   g_off[RMAX + 1];
__device__ int   g_cur[RMAX];
struct Counters { int cnt[RMAX]; int deg[NMAX]; int done; };
__device__ Counters g_c;

// ---- launch 1: basis | node hs/ht | histogram (+ last-block scan) -------------
__global__ void __launch_bounds__(256)
k_pre(const float* __restrict__ weight,    // [NB,32,32]
      const float* __restrict__ w_comp,    // [R,NB]
      const float* __restrict__ node_feat, // [N,32]
      const float* __restrict__ A_w,       // [32,128]
      const float* __restrict__ A_b,       // [32]
      const int*   __restrict__ edges,     // [2,E]
      const int*   __restrict__ rels,      // [E]
      int NB, int R, int N, int E, int nbNode, int nbHist)
{
    int b = blockIdx.x;
    const int tid = threadIdx.x;

    if (b < R) {                                    // --- basis expansion ---
        const float* wc = w_comp + b * NB;
        for (int io = tid; io < 1024; io += 256) {
            float acc = 0.f;
            for (int k = 0; k < NB; ++k)
                acc = fmaf(__ldg(wc + k), __ldg(weight + k * 1024 + io), acc);
            g_relw[b * 1024 + io] = acc;
        }
        return;
    }
    b -= R;

    if (b < nbNode) {                               // --- node hs / ht (f32x2) ---
        __shared__ float sA[32 * 129];
        for (int idx = tid; idx < 4096; idx += 256)
            sA[(idx >> 7) * 129 + (idx & 127)] = __ldg(A_w + idx);
        __syncthreads();

        const int lane = tid & 31;
        const int warp = tid >> 5;
        u64 aP[32];                 // (aws[i], awt[i]) packed
#pragma unroll
        for (int i = 0; i < 32; ++i)
            aP[i] = pk2(sA[lane * 129 + i], sA[lane * 129 + 32 + i]);
        const float ab = __ldg(A_b + lane);
#pragma unroll
        for (int k = 0; k < 4; ++k) {
            const int n = b * 32 + warp * 4 + k;
            if (n < N) {
                const float4* fp = (const float4*)(node_feat + (size_t)n * 32);
                u64 acc = pk2(ab, 0.f);
#pragma unroll
                for (int c = 0; c < 8; ++c) {
                    float4 f = __ldg(fp + c);
                    fma2(acc, pk2(f.x, f.x), aP[4*c+0]);
                    fma2(acc, pk2(f.y, f.y), aP[4*c+1]);
                    fma2(acc, pk2(f.z, f.z), aP[4*c+2]);
                    fma2(acc, pk2(f.w, f.w), aP[4*c+3]);
                }
                float hs, ht; upk(acc, hs, ht);
                g_hs[(size_t)n * 32 + lane] = hs;
                g_ht[(size_t)n * 32 + lane] = ht;
            }
        }
        return;
    }
    b -= nbNode;

    // --- histogram: smem rel counts + global deg counts ---
    __shared__ int sh[RMAX];
    for (int i = tid; i < RMAX; i += 256) sh[i] = 0;
    __syncthreads();
    const int base = b * 4096;
#pragma unroll
    for (int k = 0; k < 16; ++k) {
        const int e = base + k * 256 + tid;
        if (e < E) {
            atomicAdd(&sh[__ldg(rels + e)], 1);
            atomicAdd(&g_c.deg[__ldg(edges + E + e)], 1);
        }
    }
    __syncthreads();
    for (int i = tid; i < RMAX; i += 256) {
        const int v = sh[i];
        if (v) atomicAdd(&g_c.cnt[i], v);
    }
    __threadfence();
    __syncthreads();
    __shared__ int s_last;
    if (tid == 0)
        s_last = (atomicAdd(&g_c.done, 1) == nbHist - 1);
    __syncthreads();
    if (s_last) {                                   // --- last block: scan ---
        __shared__ int buf[RMAX];
        const int c = atomicAdd(&g_c.cnt[tid], 0);  // coherent read
        buf[tid] = c;
        __syncthreads();
#pragma unroll
        for (int d = 1; d < RMAX; d <<= 1) {
            const int v = (tid >= d) ? buf[tid - d] : 0;
            __syncthreads();
            buf[tid] += v;
            __syncthreads();
        }
        if (tid == 0) g_off[0] = 0;
        g_off[tid + 1] = buf[tid];
        g_cur[tid]     = buf[tid] - c;              // exclusive
    }
}

// ---- launch 2: out init | scatter | attention scalars --------------------------
__global__ void __launch_bounds__(256)
k_mid(const float* __restrict__ node_feat,
      const float* __restrict__ slw,   // [32,32]
      const float* __restrict__ ttr,   // [E,32]
      const float* __restrict__ tre,   // [E,32]
      const float* __restrict__ A_w,   // [32,128]
      const float* __restrict__ B_w,   // [32]
      const float* __restrict__ B_b,   // [1]
      const int*   __restrict__ edges, // [2,E]
      const int*   __restrict__ rels,  // [E]
      float*       __restrict__ out,
      int N, int E, int nbNode, int nbHist, int nbEdge)
{
    int b = blockIdx.x;
    const int tid  = threadIdx.x;
    const int lane = tid & 31;
    const int warp = tid >> 5;

    if (b < nbNode) {                               // --- out = deg*(feat@slw) ---
        float slc[32];
#pragma unroll
        for (int i = 0; i < 32; ++i) slc[i] = __ldg(slw + i * 32 + lane);
#pragma unroll
        for (int k = 0; k < 4; ++k) {
            const int n = b * 32 + warp * 4 + k;
            if (n < N) {
                const float4* fp = (const float4*)(node_feat + (size_t)n * 32);
                float s0 = 0.f, s1 = 0.f;
#pragma unroll
                for (int c = 0; c < 8; ++c) {
                    float4 f = __ldg(fp + c);
                    s0 = fmaf(f.x, slc[4*c+0], s0); s1 = fmaf(f.y, slc[4*c+1], s1);
                    s0 = fmaf(f.z, slc[4*c+2], s0); s1 = fmaf(f.w, slc[4*c+3], s1);
                }
                out[(size_t)n * 32 + lane] = (float)__ldg(&g_c.deg[n]) * (s0 + s1);
            }
        }
        return;
    }
    b -= nbNode;

    if (b < nbHist) {                               // --- scatter (sorted arrays) ---
        __shared__ int h[RMAX];
        __shared__ int cur[RMAX];
        for (int i = tid; i < RMAX; i += 256) h[i] = 0;
        __syncthreads();
        const int base = b * 4096;
        int rr[16];
#pragma unroll
        for (int k = 0; k < 16; ++k) {
            const int e = base + k * 256 + tid;
            rr[k] = (e < E) ? __ldg(rels + e) : -1;
            if (rr[k] >= 0) atomicAdd(&h[rr[k]], 1);
        }
        __syncthreads();
        for (int i = tid; i < RMAX; i += 256) {
            const int v = h[i];
            cur[i] = v ? atomicAdd(&g_cur[i], v) : 0;
        }
        __syncthreads();
#pragma unroll
        for (int k = 0; k < 16; ++k) {
            if (rr[k] >= 0) {
                const int e   = base + k * 256 + tid;
                const int pos = atomicAdd(&cur[rr[k]], 1);
                g_ssrc[pos] = __ldg(edges + e);
                g_stgt[pos] = __ldg(edges + E + e);
                g_seid[pos] = e;
            }
        }
        return;
    }
    b -= nbHist;

    // --- attention scalars: A_w smem-staged, f32x2 FMA, ILP = 4 (clamped) ---
    __shared__ float sA[32 * 129];
    for (int idx = tid; idx < 4096; idx += 256)
        sA[(idx >> 7) * 129 + (idx & 127)] = __ldg(A_w + idx);
    __syncthreads();

    u64 areP[16], atrP[16];
#pragma unroll
    for (int i = 0; i < 16; ++i) {
        areP[i] = pk2(sA[lane * 129 + 64 + 2*i], sA[lane * 129 + 64 + 2*i + 1]);
        atrP[i] = pk2(sA[lane * 129 + 96 + 2*i], sA[lane * 129 + 96 + 2*i + 1]);
    }
    const float bw = __ldg(B_w + lane);
    const float bb = __ldg(B_b);

    const int gw = b * 8 + warp;
    const int nw = nbEdge * 8;

    for (int e0 = gw * 4; e0 < E; e0 += nw * 4) {
        int ea[4], ss[4], tt[4];
#pragma unroll
        for (int k = 0; k < 4; ++k) {
            ea[k] = min(e0 + k, E - 1);             // always in-bounds
            ss[k] = __ldg(edges + ea[k]);
            tt[k] = __ldg(edges + E + ea[k]);
        }
        float hh[4];
#pragma unroll
        for (int k = 0; k < 4; ++k)
            hh[k] = __ldg(&g_hs[(size_t)ss[k] * 32 + lane])
                  + __ldg(&g_ht[(size_t)tt[k] * 32 + lane]);

        u64 acc[4] = {0ull, 0ull, 0ull, 0ull};
#pragma unroll
        for (int c = 0; c < 8; ++c) {
#pragma unroll
            for (int k = 0; k < 4; ++k) {
                ulonglong2 X = __ldg((const ulonglong2*)(tre + (size_t)ea[k] * 32) + c);
                ulonglong2 Y = __ldg((const ulonglong2*)(ttr + (size_t)ea[k] * 32) + c);
                fma2(acc[k], X.x, areP[2*c]);  fma2(acc[k], X.y, areP[2*c+1]);
                fma2(acc[k], Y.x, atrP[2*c]);  fma2(acc[k], Y.y, atrP[2*c+1]);
            }
        }
        float p[4];
#pragma unroll
        for (int k = 0; k < 4; ++k)
            p[k] = fmaxf(hh[k] + upk_sum(acc[k]), 0.f) * bw;
#pragma unroll
        for (int o = 16; o; o >>= 1) {
#pragma unroll
            for (int k = 0; k < 4; ++k)
                p[k] += __shfl_xor_sync(0xffffffffu, p[k], o);
        }
        if (lane == 0) {
#pragma unroll
            for (int k = 0; k < 4; ++k)
                if (e0 + k < E)
                    g_att[ea[k]] = 1.f / (1.f + __expf(-(p[k] + bb)));
        }
    }
}

// ---- launch 3: per-relation message + scatter-add, f32x2, ILP = 4 --------------
__global__ void __launch_bounds__(256)
k_main(const float* __restrict__ node_feat,
       float*       __restrict__ out)
{
    const int r     = blockIdx.x;
    const int start = __ldg(&g_off[r]);
    const int end   = __ldg(&g_off[r + 1]);
    if (start >= end) return;

    const int lane = threadIdx.x & 31;
    u64 rwcP[16];                       // column `lane` of rel_w[r], packed pairs
#pragma unroll
    for (int i = 0; i < 16; ++i)
        rwcP[i] = pk2(__ldg(&g_relw[r * 1024 + (2*i)   * 32 + lane]),
                      __ldg(&g_relw[r * 1024 + (2*i+1) * 32 + lane]));

    const int w = blockIdx.y * 8 + (threadIdx.x >> 5);
    const int W = gridDim.y * 8;

    for (int i0 = start + w * 4; i0 < end; i0 += W * 4) {
        int ii[4], tt[4];
        float att[4];
#pragma unroll
        for (int k = 0; k < 4; ++k) {
            ii[k] = min(i0 + k, end - 1);           // always in-bounds
            tt[k] = __ldg(&g_stgt[ii[k]]);
            att[k] = (i0 + k < end) ? __ldg(&g_att[__ldg(&g_seid[ii[k]])]) : 0.f;
        }

        u64 acc[4] = {0ull, 0ull, 0ull, 0ull};
#pragma unroll
        for (int c = 0; c < 8; ++c) {
#pragma unroll
            for (int k = 0; k < 4; ++k) {
                ulonglong2 F = __ldg((const ulonglong2*)
                    (node_feat + (size_t)__ldg(&g_ssrc[ii[k]]) * 32) + c);
                fma2(acc[k], F.x, rwcP[2*c]);
                fma2(acc[k], F.y, rwcP[2*c+1]);
            }
        }
        float v[4];
#pragma unroll
        for (int k = 0; k < 4; ++k)
            v[k] = upk_sum(acc[k]) * att[k];

        // all 32 lanes issue one red.v4: lane group k = edge k, 8 lanes each
        const int kk = lane >> 3;           // which edge this lane stores
        const int g0 = (lane & 7) * 4;      // feature offset
        float q0 = 0.f, q1 = 0.f, q2 = 0.f, q3 = 0.f;
#pragma unroll
        for (int k = 0; k < 4; ++k) {
            float a = __shfl_sync(0xffffffffu, v[k], g0 + 0);
            float bq = __shfl_sync(0xffffffffu, v[k], g0 + 1);
            float cq = __shfl_sync(0xffffffffu, v[k], g0 + 2);
            float dq = __shfl_sync(0xffffffffu, v[k], g0 + 3);
            if (kk == k) { q0 = a; q1 = bq; q2 = cq; q3 = dq; }
        }
        if (i0 + kk < end) {
            float* p = out + (size_t)tt[kk] * 32 + g0;
            asm volatile("red.global.add.v4.f32 [%0], {%1, %2, %3, %4};"
                         :: "l"(p), "f"(q0), "f"(q1), "f"(q2), "f"(q3) : "memory");
        }
    }
}

extern "C" void kernel_launch(void* const* d_in, const int* in_sizes, int n_in,
                              void* d_out, int out_size)
{
    const float* node_feat = (const float*)d_in[0];
    const float* ttr       = (const float*)d_in[1];
    const float* tre       = (const float*)d_in[2];
    const float* weight    = (const float*)d_in[3];
    const float* w_comp    = (const float*)d_in[4];
    const float* slw       = (const float*)d_in[5];
    const float* A_w       = (const float*)d_in[6];
    const float* A_b       = (const float*)d_in[7];
    const float* B_w       = (const float*)d_in[8];
    const float* B_b       = (const float*)d_in[9];
    const int*   edges     = (const int*)d_in[10];
    const int*   rels      = (const int*)d_in[11];
    float* out = (float*)d_out;

    const int E  = in_sizes[11];
    const int N  = in_sizes[0] / 32;
    const int NB = in_sizes[3] / 1024;
    const int R  = in_sizes[4] / NB;

    int sms = 148;
    cudaDeviceGetAttribute(&sms, cudaDevAttrMultiProcessorCount, 0);

    const int nbNode = (N + 31) / 32;
    const int nbHist = (E + 4095) / 4096;
    const int nbEdge = sms * 4;

    void* cptr = nullptr;
    cudaGetSymbolAddress(&cptr, g_c);
    cudaMemsetAsync(cptr, 0, sizeof(Counters));

    k_pre<<<R + nbNode + nbHist, 256>>>(weight, w_comp, node_feat, A_w, A_b,
                                        edges, rels, NB, R, N, E, nbNode, nbHist);
    k_mid<<<nbNode + nbHist + nbEdge, 256>>>(node_feat, slw, ttr, tre, A_w,
                                             B_w, B_b, edges, rels, out,
                                             N, E, nbNode, nbHist, nbEdge);
    k_main<<<dim3(R, 8), 256>>>(node_feat, out);
}

// round 9
// speedup vs baseline: 2.4095x; 1.0325x over previous
#include <cuda_runtime.h>
#include <cuda_bf16.h>

// ---------------------------------------------------------------------------
// RGCN layer, 3-launch pipeline (latency-optimized):
//  memset : zero counters
//  k_pre  : basis expansion | node hs/ht (A_w smem-staged, 128 nodes/block)
//           | rel+deg histogram + last-block scan
//  k_mid  : out init (deg*(feat@slw), 128 nodes/block) | counting-sort scatter
//           | per-edge attention scalar (f32x2 FMA, ILP=4, clamped indices)
//  k_main : per-relation blocks, rel_w f32x2, ILP=4, full-warp red.v4
// ---------------------------------------------------------------------------

#define RMAX 256
#define NMAX 16384
#define EMAX 262144

typedef unsigned long long u64;

__device__ __forceinline__ u64 pk2(float lo, float hi) {
    u64 r; asm("mov.b64 %0, {%1, %2};" : "=l"(r) : "f"(lo), "f"(hi)); return r;
}
__device__ __forceinline__ void fma2(u64& d, u64 a, u64 b) {
    asm("fma.rn.f32x2 %0, %1, %2, %0;" : "+l"(d) : "l"(a), "l"(b));
}
__device__ __forceinline__ float upk_sum(u64 v) {
    float lo, hi; asm("mov.b64 {%0, %1}, %2;" : "=f"(lo), "=f"(hi) : "l"(v));
    return lo + hi;
}

__device__ float g_relw[RMAX * 1024];
__device__ float g_hs[NMAX * 32];
__device__ float g_ht[NMAX * 32];
__device__ float g_att[EMAX];
__device__ int   g_ssrc[EMAX];
__device__ int   g_stgt[EMAX];
__device__ int   g_seid[EMAX];
__device__ int   g_off[RMAX + 1];
__device__ int   g_cur[RMAX];
struct Counters { int cnt[RMAX]; int deg[NMAX]; int done; };
__device__ Counters g_c;

// ---- launch 1: basis | node hs/ht | histogram (+ last-block scan) -------------
__global__ void __launch_bounds__(256)
k_pre(const float* __restrict__ weight,    // [NB,32,32]
      const float* __restrict__ w_comp,    // [R,NB]
      const float* __restrict__ node_feat, // [N,32]
      const float* __restrict__ A_w,       // [32,128]
      const float* __restrict__ A_b,       // [32]
      const int*   __restrict__ edges,     // [2,E]
      const int*   __restrict__ rels,      // [E]
      int NB, int R, int N, int E, int nbNode, int nbHist)
{
    int b = blockIdx.x;
    const int tid = threadIdx.x;

    if (b < R) {                                    // --- basis expansion ---
        const float* wc = w_comp + b * NB;
        for (int io = tid; io < 1024; io += 256) {
            float acc = 0.f;
            for (int k = 0; k < NB; ++k)
                acc = fmaf(__ldg(wc + k), __ldg(weight + k * 1024 + io), acc);
            g_relw[b * 1024 + io] = acc;
        }
        return;
    }
    b -= R;

    if (b < nbNode) {                               // --- node hs / ht ---
        __shared__ float sA[32 * 129];
        for (int idx = tid; idx < 4096; idx += 256)
            sA[(idx >> 7) * 129 + (idx & 127)] = __ldg(A_w + idx);
        __syncthreads();

        const int lane = tid & 31;
        const int warp = tid >> 5;
        float aws[32], awt[32];
#pragma unroll
        for (int i = 0; i < 32; ++i) {
            aws[i] = sA[lane * 129 + i];
            awt[i] = sA[lane * 129 + 32 + i];
        }
        const float ab = __ldg(A_b + lane);
        // 128 nodes per block, 16 per warp
#pragma unroll
        for (int k = 0; k < 16; ++k) {
            const int n = b * 128 + warp * 16 + k;
            if (n < N) {
                const float4* fp = (const float4*)(node_feat + (size_t)n * 32);
                float hs = ab, ht = 0.f;
#pragma unroll
                for (int c = 0; c < 8; ++c) {
                    float4 f = __ldg(fp + c);
                    hs = fmaf(f.x, aws[4*c+0], hs); ht = fmaf(f.x, awt[4*c+0], ht);
                    hs = fmaf(f.y, aws[4*c+1], hs); ht = fmaf(f.y, awt[4*c+1], ht);
                    hs = fmaf(f.z, aws[4*c+2], hs); ht = fmaf(f.z, awt[4*c+2], ht);
                    hs = fmaf(f.w, aws[4*c+3], hs); ht = fmaf(f.w, awt[4*c+3], ht);
                }
                g_hs[(size_t)n * 32 + lane] = hs;
                g_ht[(size_t)n * 32 + lane] = ht;
            }
        }
        return;
    }
    b -= nbNode;

    // --- histogram: smem rel counts + global deg counts ---
    __shared__ int sh[RMAX];
    for (int i = tid; i < RMAX; i += 256) sh[i] = 0;
    __syncthreads();
    const int base = b * 4096;
#pragma unroll
    for (int k = 0; k < 16; ++k) {
        const int e = base + k * 256 + tid;
        if (e < E) {
            atomicAdd(&sh[__ldg(rels + e)], 1);
            atomicAdd(&g_c.deg[__ldg(edges + E + e)], 1);
        }
    }
    __syncthreads();
    for (int i = tid; i < RMAX; i += 256) {
        const int v = sh[i];
        if (v) atomicAdd(&g_c.cnt[i], v);
    }
    __threadfence();
    __syncthreads();
    __shared__ int s_last;
    if (tid == 0)
        s_last = (atomicAdd(&g_c.done, 1) == nbHist - 1);
    __syncthreads();
    if (s_last) {                                   // --- last block: scan ---
        __shared__ int buf[RMAX];
        const int c = atomicAdd(&g_c.cnt[tid], 0);  // coherent read
        buf[tid] = c;
        __syncthreads();
#pragma unroll
        for (int d = 1; d < RMAX; d <<= 1) {
            const int v = (tid >= d) ? buf[tid - d] : 0;
            __syncthreads();
            buf[tid] += v;
            __syncthreads();
        }
        if (tid == 0) g_off[0] = 0;
        g_off[tid + 1] = buf[tid];
        g_cur[tid]     = buf[tid] - c;              // exclusive
    }
}

// ---- launch 2: out init | scatter | attention scalars --------------------------
__global__ void __launch_bounds__(256)
k_mid(const float* __restrict__ node_feat,
      const float* __restrict__ slw,   // [32,32]
      const float* __restrict__ ttr,   // [E,32]
      const float* __restrict__ tre,   // [E,32]
      const float* __restrict__ A_w,   // [32,128]
      const float* __restrict__ B_w,   // [32]
      const float* __restrict__ B_b,   // [1]
      const int*   __restrict__ edges, // [2,E]
      const int*   __restrict__ rels,  // [E]
      float*       __restrict__ out,
      int N, int E, int nbNode, int nbHist, int nbEdge)
{
    int b = blockIdx.x;
    const int tid  = threadIdx.x;
    const int lane = tid & 31;
    const int warp = tid >> 5;

    if (b < nbNode) {                               // --- out = deg*(feat@slw) ---
        float slc[32];
#pragma unroll
        for (int i = 0; i < 32; ++i) slc[i] = __ldg(slw + i * 32 + lane);
        // 128 nodes per block, 16 per warp
#pragma unroll
        for (int k = 0; k < 16; ++k) {
            const int n = b * 128 + warp * 16 + k;
            if (n < N) {
                const float4* fp = (const float4*)(node_feat + (size_t)n * 32);
                float s0 = 0.f, s1 = 0.f;
#pragma unroll
                for (int c = 0; c < 8; ++c) {
                    float4 f = __ldg(fp + c);
                    s0 = fmaf(f.x, slc[4*c+0], s0); s1 = fmaf(f.y, slc[4*c+1], s1);
                    s0 = fmaf(f.z, slc[4*c+2], s0); s1 = fmaf(f.w, slc[4*c+3], s1);
                }
                out[(size_t)n * 32 + lane] = (float)__ldg(&g_c.deg[n]) * (s0 + s1);
            }
        }
        return;
    }
    b -= nbNode;

    if (b < nbHist) {                               // --- scatter (sorted arrays) ---
        __shared__ int h[RMAX];
        __shared__ int cur[RMAX];
        for (int i = tid; i < RMAX; i += 256) h[i] = 0;
        __syncthreads();
        const int base = b * 4096;
        int rr[16];
#pragma unroll
        for (int k = 0; k < 16; ++k) {
            const int e = base + k * 256 + tid;
            rr[k] = (e < E) ? __ldg(rels + e) : -1;
            if (rr[k] >= 0) atomicAdd(&h[rr[k]], 1);
        }
        __syncthreads();
        for (int i = tid; i < RMAX; i += 256) {
            const int v = h[i];
            cur[i] = v ? atomicAdd(&g_cur[i], v) : 0;
        }
        __syncthreads();
#pragma unroll
        for (int k = 0; k < 16; ++k) {
            if (rr[k] >= 0) {
                const int e   = base + k * 256 + tid;
                const int pos = atomicAdd(&cur[rr[k]], 1);
                g_ssrc[pos] = __ldg(edges + e);
                g_stgt[pos] = __ldg(edges + E + e);
                g_seid[pos] = e;
            }
        }
        return;
    }
    b -= nbHist;

    // --- attention scalars: A_w smem-staged, f32x2 FMA, ILP = 4 (clamped) ---
    __shared__ float sA[32 * 129];
    for (int idx = tid; idx < 4096; idx += 256)
        sA[(idx >> 7) * 129 + (idx & 127)] = __ldg(A_w + idx);
    __syncthreads();

    u64 areP[16], atrP[16];
#pragma unroll
    for (int i = 0; i < 16; ++i) {
        areP[i] = pk2(sA[lane * 129 + 64 + 2*i], sA[lane * 129 + 64 + 2*i + 1]);
        atrP[i] = pk2(sA[lane * 129 + 96 + 2*i], sA[lane * 129 + 96 + 2*i + 1]);
    }
    const float bw = __ldg(B_w + lane);
    const float bb = __ldg(B_b);

    const int gw = b * 8 + warp;
    const int nw = nbEdge * 8;

    for (int e0 = gw * 4; e0 < E; e0 += nw * 4) {
        int ea[4], ss[4], tt[4];
#pragma unroll
        for (int k = 0; k < 4; ++k) {
            ea[k] = min(e0 + k, E - 1);             // always in-bounds
            ss[k] = __ldg(edges + ea[k]);
            tt[k] = __ldg(edges + E + ea[k]);
        }
        float hh[4];
#pragma unroll
        for (int k = 0; k < 4; ++k)
            hh[k] = __ldg(&g_hs[(size_t)ss[k] * 32 + lane])
                  + __ldg(&g_ht[(size_t)tt[k] * 32 + lane]);

        u64 acc[4] = {0ull, 0ull, 0ull, 0ull};
#pragma unroll
        for (int c = 0; c < 8; ++c) {
#pragma unroll
            for (int k = 0; k < 4; ++k) {
                ulonglong2 X = __ldg((const ulonglong2*)(tre + (size_t)ea[k] * 32) + c);
                ulonglong2 Y = __ldg((const ulonglong2*)(ttr + (size_t)ea[k] * 32) + c);
                fma2(acc[k], X.x, areP[2*c]);  fma2(acc[k], X.y, areP[2*c+1]);
                fma2(acc[k], Y.x, atrP[2*c]);  fma2(acc[k], Y.y, atrP[2*c+1]);
            }
        }
        float p[4];
#pragma unroll
        for (int k = 0; k < 4; ++k)
            p[k] = fmaxf(hh[k] + upk_sum(acc[k]), 0.f) * bw;
#pragma unroll
        for (int o = 16; o; o >>= 1) {
#pragma unroll
            for (int k = 0; k < 4; ++k)
                p[k] += __shfl_xor_sync(0xffffffffu, p[k], o);
        }
        if (lane == 0) {
#pragma unroll
            for (int k = 0; k < 4; ++k)
                if (e0 + k < E)
                    g_att[ea[k]] = 1.f / (1.f + __expf(-(p[k] + bb)));
        }
    }
}

// ---- launch 3: per-relation message + scatter-add, f32x2, ILP = 4 --------------
__global__ void __launch_bounds__(256)
k_main(const float* __restrict__ node_feat,
       float*       __restrict__ out)
{
    const int r     = blockIdx.x;
    const int start = __ldg(&g_off[r]);
    const int end   = __ldg(&g_off[r + 1]);
    if (start >= end) return;

    const int lane = threadIdx.x & 31;
    u64 rwcP[16];                       // column `lane` of rel_w[r], packed pairs
#pragma unroll
    for (int i = 0; i < 16; ++i)
        rwcP[i] = pk2(__ldg(&g_relw[r * 1024 + (2*i)   * 32 + lane]),
                      __ldg(&g_relw[r * 1024 + (2*i+1) * 32 + lane]));

    const int w = blockIdx.y * 8 + (threadIdx.x >> 5);
    const int W = gridDim.y * 8;

    for (int i0 = start + w * 4; i0 < end; i0 += W * 4) {
        int ii[4], tt[4];
        float att[4];
#pragma unroll
        for (int k = 0; k < 4; ++k) {
            ii[k] = min(i0 + k, end - 1);           // always in-bounds
            tt[k] = __ldg(&g_stgt[ii[k]]);
            att[k] = (i0 + k < end) ? __ldg(&g_att[__ldg(&g_seid[ii[k]])]) : 0.f;
        }

        u64 acc[4] = {0ull, 0ull, 0ull, 0ull};
#pragma unroll
        for (int c = 0; c < 8; ++c) {
#pragma unroll
            for (int k = 0; k < 4; ++k) {
                ulonglong2 F = __ldg((const ulonglong2*)
                    (node_feat + (size_t)__ldg(&g_ssrc[ii[k]]) * 32) + c);
                fma2(acc[k], F.x, rwcP[2*c]);
                fma2(acc[k], F.y, rwcP[2*c+1]);
            }
        }
        float v[4];
#pragma unroll
        for (int k = 0; k < 4; ++k)
            v[k] = upk_sum(acc[k]) * att[k];

        // all 32 lanes issue one red.v4: lane group k = edge k, 8 lanes each
        const int kk = lane >> 3;           // which edge this lane stores
        const int g0 = (lane & 7) * 4;      // feature offset
        float q0 = 0.f, q1 = 0.f, q2 = 0.f, q3 = 0.f;
#pragma unroll
        for (int k = 0; k < 4; ++k) {
            float a = __shfl_sync(0xffffffffu, v[k], g0 + 0);
            float bq = __shfl_sync(0xffffffffu, v[k], g0 + 1);
            float cq = __shfl_sync(0xffffffffu, v[k], g0 + 2);
            float dq = __shfl_sync(0xffffffffu, v[k], g0 + 3);
            if (kk == k) { q0 = a; q1 = bq; q2 = cq; q3 = dq; }
        }
        if (i0 + kk < end) {
            float* p = out + (size_t)tt[kk] * 32 + g0;
            asm volatile("red.global.add.v4.f32 [%0], {%1, %2, %3, %4};"
                         :: "l"(p), "f"(q0), "f"(q1), "f"(q2), "f"(q3) : "memory");
        }
    }
}

extern "C" void kernel_launch(void* const* d_in, const int* in_sizes, int n_in,
                              void* d_out, int out_size)
{
    const float* node_feat = (const float*)d_in[0];
    const float* ttr       = (const float*)d_in[1];
    const float* tre       = (const float*)d_in[2];
    const float* weight    = (const float*)d_in[3];
    const float* w_comp    = (const float*)d_in[4];
    const float* slw       = (const float*)d_in[5];
    const float* A_w       = (const float*)d_in[6];
    const float* A_b       = (const float*)d_in[7];
    const float* B_w       = (const float*)d_in[8];
    const float* B_b       = (const float*)d_in[9];
    const int*   edges     = (const int*)d_in[10];
    const int*   rels      = (const int*)d_in[11];
    float* out = (float*)d_out;

    const int E  = in_sizes[11];
    const int N  = in_sizes[0] / 32;
    const int NB = in_sizes[3] / 1024;
    const int R  = in_sizes[4] / NB;

    int sms = 148;
    cudaDeviceGetAttribute(&sms, cudaDevAttrMultiProcessorCount, 0);

    const int nbNode = (N + 127) / 128;
    const int nbHist = (E + 4095) / 4096;
    const int nbEdge = sms * 4;

    void* cptr = nullptr;
    cudaGetSymbolAddress(&cptr, g_c);
    cudaMemsetAsync(cptr, 0, sizeof(Counters));

    k_pre<<<R + nbNode + nbHist, 256>>>(weight, w_comp, node_feat, A_w, A_b,
                                        edges, rels, NB, R, N, E, nbNode, nbHist);
    k_mid<<<nbNode + nbHist + nbEdge, 256>>>(node_feat, slw, ttr, tre, A_w,
                                             B_w, B_b, edges, rels, out,
                                             N, E, nbNode, nbHist, nbEdge);
    k_main<<<dim3(R, 8), 256>>>(node_feat, out);
}

// round 10
// speedup vs baseline: 2.4528x; 1.0180x over previous
#include <cuda_runtime.h>
#include <cuda_bf16.h>

// ---------------------------------------------------------------------------
// RGCN layer, 3 launches + 2 memsets:
//  k_pre  : basis expansion | node hs/ht/sl (A_w smem-staged)
//           | relation histogram + last-block scan
//  k_scat : counting-sort scatter (sorted src/tgt/eid)
//  k_main : per-relation blocks; FUSED attention + message + self-loop;
//           rel_w f32x2 in regs, are/atr in smem, ILP=4, full-warp red.v4
// ---------------------------------------------------------------------------

#define RMAX 256
#define NMAX 16384
#define EMAX 262144

typedef unsigned long long u64;

__device__ __forceinline__ u64 pk2(float lo, float hi) {
    u64 r; asm("mov.b64 %0, {%1, %2};" : "=l"(r) : "f"(lo), "f"(hi)); return r;
}
__device__ __forceinline__ void fma2(u64& d, u64 a, u64 b) {
    asm("fma.rn.f32x2 %0, %1, %2, %0;" : "+l"(d) : "l"(a), "l"(b));
}
__device__ __forceinline__ float upk_sum(u64 v) {
    float lo, hi; asm("mov.b64 {%0, %1}, %2;" : "=f"(lo), "=f"(hi) : "l"(v));
    return lo + hi;
}

__device__ float g_relw[RMAX * 1024];
__device__ float g_hs[NMAX * 32];
__device__ float g_ht[NMAX * 32];
__device__ float g_sl[NMAX * 32];
__device__ int   g_ssrc[EMAX];
__device__ int   g_stgt[EMAX];
__device__ int   g_seid[EMAX];
__device__ int   g_off[RMAX + 1];
__device__ int   g_cur[RMAX];
struct Counters { int cnt[RMAX]; int done; };
__device__ Counters g_c;

// ---- launch 1: basis | node hs/ht/sl | rel histogram + scan --------------------
__global__ void __launch_bounds__(256)
k_pre(const float* __restrict__ weight,    // [NB,32,32]
      const float* __restrict__ w_comp,    // [R,NB]
      const float* __restrict__ node_feat, // [N,32]
      const float* __restrict__ A_w,       // [32,128]
      const float* __restrict__ A_b,       // [32]
      const float* __restrict__ slw,       // [32,32]
      const int*   __restrict__ rels,      // [E]
      int NB, int R, int N, int E, int nbNode, int nbHist)
{
    int b = blockIdx.x;
    const int tid = threadIdx.x;

    if (b < R) {                                    // --- basis expansion ---
        const float* wc = w_comp + b * NB;
        for (int io = tid; io < 1024; io += 256) {
            float acc = 0.f;
            for (int k = 0; k < NB; ++k)
                acc = fmaf(__ldg(wc + k), __ldg(weight + k * 1024 + io), acc);
            g_relw[b * 1024 + io] = acc;
        }
        return;
    }
    b -= R;

    if (b < nbNode) {                               // --- node hs / ht / sl ---
        __shared__ float sA[32 * 129];
        for (int idx = tid; idx < 4096; idx += 256)
            sA[(idx >> 7) * 129 + (idx & 127)] = __ldg(A_w + idx);
        __syncthreads();

        const int lane = tid & 31;
        const int warp = tid >> 5;
        float aws[32], awt[32], slc[32];
#pragma unroll
        for (int i = 0; i < 32; ++i) {
            aws[i] = sA[lane * 129 + i];
            awt[i] = sA[lane * 129 + 32 + i];
            slc[i] = __ldg(slw + i * 32 + lane);    // coalesced
        }
        const float ab = __ldg(A_b + lane);
        // 64 nodes per block, 8 per warp
#pragma unroll
        for (int k = 0; k < 8; ++k) {
            const int n = b * 64 + warp * 8 + k;
            if (n < N) {
                const float4* fp = (const float4*)(node_feat + (size_t)n * 32);
                float hs = ab, ht = 0.f, sl = 0.f;
#pragma unroll
                for (int c = 0; c < 8; ++c) {
                    float4 f = __ldg(fp + c);
                    hs = fmaf(f.x, aws[4*c+0], hs); ht = fmaf(f.x, awt[4*c+0], ht); sl = fmaf(f.x, slc[4*c+0], sl);
                    hs = fmaf(f.y, aws[4*c+1], hs); ht = fmaf(f.y, awt[4*c+1], ht); sl = fmaf(f.y, slc[4*c+1], sl);
                    hs = fmaf(f.z, aws[4*c+2], hs); ht = fmaf(f.z, awt[4*c+2], ht); sl = fmaf(f.z, slc[4*c+2], sl);
                    hs = fmaf(f.w, aws[4*c+3], hs); ht = fmaf(f.w, awt[4*c+3], ht); sl = fmaf(f.w, slc[4*c+3], sl);
                }
                g_hs[(size_t)n * 32 + lane] = hs;
                g_ht[(size_t)n * 32 + lane] = ht;
                g_sl[(size_t)n * 32 + lane] = sl;
            }
        }
        return;
    }
    b -= nbNode;

    // --- relation histogram (2048 edges/block) + last-block scan ---
    __shared__ int sh[RMAX];
    for (int i = tid; i < RMAX; i += 256) sh[i] = 0;
    __syncthreads();
    const int base = b * 2048;
#pragma unroll
    for (int k = 0; k < 8; ++k) {
        const int e = base + k * 256 + tid;
        if (e < E) atomicAdd(&sh[__ldg(rels + e)], 1);
    }
    __syncthreads();
    for (int i = tid; i < RMAX; i += 256) {
        const int v = sh[i];
        if (v) atomicAdd(&g_c.cnt[i], v);
    }
    __threadfence();
    __syncthreads();
    __shared__ int s_last;
    if (tid == 0)
        s_last = (atomicAdd(&g_c.done, 1) == nbHist - 1);
    __syncthreads();
    if (s_last) {                                   // --- last block: scan ---
        __shared__ int buf[RMAX];
        const int c = atomicAdd(&g_c.cnt[tid], 0);  // coherent read
        buf[tid] = c;
        __syncthreads();
#pragma unroll
        for (int d = 1; d < RMAX; d <<= 1) {
            const int v = (tid >= d) ? buf[tid - d] : 0;
            __syncthreads();
            buf[tid] += v;
            __syncthreads();
        }
        if (tid == 0) g_off[0] = 0;
        g_off[tid + 1] = buf[tid];
        g_cur[tid]     = buf[tid] - c;              // exclusive
    }
}

// ---- launch 2: counting-sort scatter --------------------------------------------
__global__ void __launch_bounds__(256)
k_scat(const int* __restrict__ edges,  // [2,E]
       const int* __restrict__ rels,   // [E]
       int E)
{
    __shared__ int h[RMAX];
    __shared__ int cur[RMAX];
    const int tid = threadIdx.x;
    for (int i = tid; i < RMAX; i += 256) h[i] = 0;
    __syncthreads();
    const int base = blockIdx.x * 2048;
    int rr[8];
#pragma unroll
    for (int k = 0; k < 8; ++k) {
        const int e = base + k * 256 + tid;
        rr[k] = (e < E) ? __ldg(rels + e) : -1;
        if (rr[k] >= 0) atomicAdd(&h[rr[k]], 1);
    }
    __syncthreads();
    for (int i = tid; i < RMAX; i += 256) {
        const int v = h[i];
        cur[i] = v ? atomicAdd(&g_cur[i], v) : 0;
    }
    __syncthreads();
#pragma unroll
    for (int k = 0; k < 8; ++k) {
        if (rr[k] >= 0) {
            const int e   = base + k * 256 + tid;
            const int pos = atomicAdd(&cur[rr[k]], 1);
            g_ssrc[pos] = __ldg(edges + e);
            g_stgt[pos] = __ldg(edges + E + e);
            g_seid[pos] = e;
        }
    }
}

// ---- launch 3: fused attention + message + self-loop, red.v4, ILP = 4 -----------
__global__ void __launch_bounds__(256)
k_main(const float* __restrict__ node_feat,
       const float* __restrict__ ttr,   // [E,32]
       const float* __restrict__ tre,   // [E,32]
       const float* __restrict__ A_w,   // [32,128]
       const float* __restrict__ B_w,   // [32]
       const float* __restrict__ B_b,   // [1]
       float*       __restrict__ out)
{
    const int r     = blockIdx.x;
    const int start = __ldg(&g_off[r]);
    const int end   = __ldg(&g_off[r + 1]);

    const int tid  = threadIdx.x;
    const int lane = tid & 31;

    // are/atr coefficients packed as f32x2 in smem: row = output lane
    __shared__ u64 sAre[32 * 17];
    __shared__ u64 sAtr[32 * 17];
    if (start < end) {
        for (int idx = tid; idx < 32 * 16; idx += 256) {
            const int row = idx >> 4, i = idx & 15;
            sAre[row * 17 + i] = pk2(__ldg(A_w + row * 128 + 64 + 2*i),
                                     __ldg(A_w + row * 128 + 64 + 2*i + 1));
            sAtr[row * 17 + i] = pk2(__ldg(A_w + row * 128 + 96 + 2*i),
                                     __ldg(A_w + row * 128 + 96 + 2*i + 1));
        }
        __syncthreads();
    }
    if (start >= end) return;

    u64 rwcP[16];                       // column `lane` of rel_w[r], packed pairs
#pragma unroll
    for (int i = 0; i < 16; ++i)
        rwcP[i] = pk2(__ldg(&g_relw[r * 1024 + (2*i)   * 32 + lane]),
                      __ldg(&g_relw[r * 1024 + (2*i+1) * 32 + lane]));

    const float bw = __ldg(B_w + lane);
    const float bb = __ldg(B_b);

    const int w = blockIdx.y * 8 + (tid >> 5);
    const int W = gridDim.y * 8;

    for (int i0 = start + w * 4; i0 < end; i0 += W * 4) {
        int ii[4], ss[4], tt[4], ee[4];
#pragma unroll
        for (int k = 0; k < 4; ++k) {
            ii[k] = min(i0 + k, end - 1);           // always in-bounds
            ss[k] = __ldg(&g_ssrc[ii[k]]);
            tt[k] = __ldg(&g_stgt[ii[k]]);
            ee[k] = __ldg(&g_seid[ii[k]]);
        }
        float hh[4], sl[4];
#pragma unroll
        for (int k = 0; k < 4; ++k) {
            hh[k] = __ldg(&g_hs[(size_t)ss[k] * 32 + lane])
                  + __ldg(&g_ht[(size_t)tt[k] * 32 + lane]);
            sl[k] = __ldg(&g_sl[(size_t)tt[k] * 32 + lane]);
        }

        u64 aacc[4] = {0ull, 0ull, 0ull, 0ull};
        u64 macc[4] = {0ull, 0ull, 0ull, 0ull};
#pragma unroll
        for (int c = 0; c < 8; ++c) {
            const u64 a0 = sAre[lane * 17 + 2*c];
            const u64 a1 = sAre[lane * 17 + 2*c + 1];
            const u64 t0 = sAtr[lane * 17 + 2*c];
            const u64 t1 = sAtr[lane * 17 + 2*c + 1];
#pragma unroll
            for (int k = 0; k < 4; ++k) {
                ulonglong2 X = __ldg((const ulonglong2*)(tre + (size_t)ee[k] * 32) + c);
                ulonglong2 Y = __ldg((const ulonglong2*)(ttr + (size_t)ee[k] * 32) + c);
                ulonglong2 F = __ldg((const ulonglong2*)(node_feat + (size_t)ss[k] * 32) + c);
                fma2(aacc[k], X.x, a0);  fma2(aacc[k], X.y, a1);
                fma2(aacc[k], Y.x, t0);  fma2(aacc[k], Y.y, t1);
                fma2(macc[k], F.x, rwcP[2*c]);
                fma2(macc[k], F.y, rwcP[2*c+1]);
            }
        }
        float p[4];
#pragma unroll
        for (int k = 0; k < 4; ++k)
            p[k] = fmaxf(hh[k] + upk_sum(aacc[k]), 0.f) * bw;
#pragma unroll
        for (int o = 16; o; o >>= 1) {
#pragma unroll
            for (int k = 0; k < 4; ++k)
                p[k] += __shfl_xor_sync(0xffffffffu, p[k], o);
        }
        float v[4];
#pragma unroll
        for (int k = 0; k < 4; ++k) {
            const float att = 1.f / (1.f + __expf(-(p[k] + bb)));
            v[k] = fmaf(upk_sum(macc[k]), att, sl[k]);
        }

        // all 32 lanes issue one red.v4: lane group k = edge k, 8 lanes each
        const int kk = lane >> 3;           // which edge this lane stores
        const int g0 = (lane & 7) * 4;      // feature offset
        float q0 = 0.f, q1 = 0.f, q2 = 0.f, q3 = 0.f;
#pragma unroll
        for (int k = 0; k < 4; ++k) {
            float a  = __shfl_sync(0xffffffffu, v[k], g0 + 0);
            float bq = __shfl_sync(0xffffffffu, v[k], g0 + 1);
            float cq = __shfl_sync(0xffffffffu, v[k], g0 + 2);
            float dq = __shfl_sync(0xffffffffu, v[k], g0 + 3);
            if (kk == k) { q0 = a; q1 = bq; q2 = cq; q3 = dq; }
        }
        if (i0 + kk < end) {
            float* p_ = out + (size_t)tt[kk] * 32 + g0;
            asm volatile("red.global.add.v4.f32 [%0], {%1, %2, %3, %4};"
                         :: "l"(p_), "f"(q0), "f"(q1), "f"(q2), "f"(q3) : "memory");
        }
    }
}

extern "C" void kernel_launch(void* const* d_in, const int* in_sizes, int n_in,
                              void* d_out, int out_size)
{
    const float* node_feat = (const float*)d_in[0];
    const float* ttr       = (const float*)d_in[1];
    const float* tre       = (const float*)d_in[2];
    const float* weight    = (const float*)d_in[3];
    const float* w_comp    = (const float*)d_in[4];
    const float* slw       = (const float*)d_in[5];
    const float* A_w       = (const float*)d_in[6];
    const float* A_b       = (const float*)d_in[7];
    const float* B_w       = (const float*)d_in[8];
    const float* B_b       = (const float*)d_in[9];
    const int*   edges     = (const int*)d_in[10];
    const int*   rels      = (const int*)d_in[11];
    float* out = (float*)d_out;

    const int E  = in_sizes[11];
    const int N  = in_sizes[0] / 32;
    const int NB = in_sizes[3] / 1024;
    const int R  = in_sizes[4] / NB;

    const int nbNode = (N + 63) / 64;
    const int nbHist = (E + 2047) / 2048;

    void* cptr = nullptr;
    cudaGetSymbolAddress(&cptr, g_c);
    cudaMemsetAsync(cptr, 0, sizeof(Counters));
    cudaMemsetAsync(d_out, 0, (size_t)out_size * sizeof(float));

    k_pre<<<R + nbNode + nbHist, 256>>>(weight, w_comp, node_feat, A_w, A_b,
                                        slw, rels, NB, R, N, E, nbNode, nbHist);
    k_scat<<<nbHist, 256>>>(edges, rels, E);
    k_main<<<dim3(R, 8), 256>>>(node_feat, ttr, tre, A_w, B_w, B_b, out);
}

// round 11
// speedup vs baseline: 2.5349x; 1.0335x over previous
#include <cuda_runtime.h>
#include <cuda_bf16.h>

// ---------------------------------------------------------------------------
// RGCN layer, 3 launches + 1 memset:
//  k_pre  : basis expansion (ILP=4) | node hs + (ht,sl) float2 (A_w smem-staged)
//           | relation histogram + last-block scan
//  k_scat : counting-sort scatter (int4 {src,tgt,eid}) | zero out
//  k_main : per-relation blocks; fused attention + message + self-loop;
//           rel_w f32x2 in regs, are/atr in smem, ILP=4, full-warp red.v4
// ---------------------------------------------------------------------------

#define RMAX 256
#define NMAX 16384
#define EMAX 262144

typedef unsigned long long u64;

__device__ __forceinline__ u64 pk2(float lo, float hi) {
    u64 r; asm("mov.b64 %0, {%1, %2};" : "=l"(r) : "f"(lo), "f"(hi)); return r;
}
__device__ __forceinline__ void fma2(u64& d, u64 a, u64 b) {
    asm("fma.rn.f32x2 %0, %1, %2, %0;" : "+l"(d) : "l"(a), "l"(b));
}
__device__ __forceinline__ float upk_sum(u64 v) {
    float lo, hi; asm("mov.b64 {%0, %1}, %2;" : "=f"(lo), "=f"(hi) : "l"(v));
    return lo + hi;
}

__device__ float  g_relw[RMAX * 1024];
__device__ float  g_hs[NMAX * 32];
__device__ float2 g_htsl[NMAX * 32];   // interleaved (ht, sl) per node/lane
__device__ int4   g_edge[EMAX];        // sorted {src, tgt, eid, 0}
__device__ int    g_off[RMAX + 1];
__device__ int    g_cur[RMAX];
struct Counters { int cnt[RMAX]; int done; };
__device__ Counters g_c;

// ---- launch 1: basis | node hs/(ht,sl) | rel histogram + scan ------------------
__global__ void __launch_bounds__(256)
k_pre(const float* __restrict__ weight,    // [NB,32,32]
      const float* __restrict__ w_comp,    // [R,NB]
      const float* __restrict__ node_feat, // [N,32]
      const float* __restrict__ A_w,       // [32,128]
      const float* __restrict__ A_b,       // [32]
      const float* __restrict__ slw,       // [32,32]
      const int*   __restrict__ rels,      // [E]
      int NB, int R, int N, int E, int nbNode, int nbHist)
{
    int b = blockIdx.x;
    const int tid = threadIdx.x;

    if (b < R) {                                    // --- basis expansion, ILP=4 ---
        const float* wc = w_comp + b * NB;
        float acc0 = 0.f, acc1 = 0.f, acc2 = 0.f, acc3 = 0.f;
        for (int k = 0; k < NB; ++k) {
            const float wcb = __ldg(wc + k);
            const float* wp = weight + k * 1024 + tid;
            acc0 = fmaf(wcb, __ldg(wp +   0), acc0);
            acc1 = fmaf(wcb, __ldg(wp + 256), acc1);
            acc2 = fmaf(wcb, __ldg(wp + 512), acc2);
            acc3 = fmaf(wcb, __ldg(wp + 768), acc3);
        }
        g_relw[b * 1024 + tid +   0] = acc0;
        g_relw[b * 1024 + tid + 256] = acc1;
        g_relw[b * 1024 + tid + 512] = acc2;
        g_relw[b * 1024 + tid + 768] = acc3;
        return;
    }
    b -= R;

    if (b < nbNode) {                               // --- node hs / (ht,sl) ---
        __shared__ float sA[32 * 129];
        for (int idx = tid; idx < 4096; idx += 256)
            sA[(idx >> 7) * 129 + (idx & 127)] = __ldg(A_w + idx);
        __syncthreads();

        const int lane = tid & 31;
        const int warp = tid >> 5;
        float aws[32], awt[32], slc[32];
#pragma unroll
        for (int i = 0; i < 32; ++i) {
            aws[i] = sA[lane * 129 + i];
            awt[i] = sA[lane * 129 + 32 + i];
            slc[i] = __ldg(slw + i * 32 + lane);    // coalesced
        }
        const float ab = __ldg(A_b + lane);
        // 64 nodes per block, 8 per warp
#pragma unroll
        for (int k = 0; k < 8; ++k) {
            const int n = b * 64 + warp * 8 + k;
            if (n < N) {
                const float4* fp = (const float4*)(node_feat + (size_t)n * 32);
                float hs = ab, ht = 0.f, sl = 0.f;
#pragma unroll
                for (int c = 0; c < 8; ++c) {
                    float4 f = __ldg(fp + c);
                    hs = fmaf(f.x, aws[4*c+0], hs); ht = fmaf(f.x, awt[4*c+0], ht); sl = fmaf(f.x, slc[4*c+0], sl);
                    hs = fmaf(f.y, aws[4*c+1], hs); ht = fmaf(f.y, awt[4*c+1], ht); sl = fmaf(f.y, slc[4*c+1], sl);
                    hs = fmaf(f.z, aws[4*c+2], hs); ht = fmaf(f.z, awt[4*c+2], ht); sl = fmaf(f.z, slc[4*c+2], sl);
                    hs = fmaf(f.w, aws[4*c+3], hs); ht = fmaf(f.w, awt[4*c+3], ht); sl = fmaf(f.w, slc[4*c+3], sl);
                }
                g_hs[(size_t)n * 32 + lane]   = hs;
                g_htsl[(size_t)n * 32 + lane] = make_float2(ht, sl);
            }
        }
        return;
    }
    b -= nbNode;

    // --- relation histogram (2048 edges/block) + last-block scan ---
    __shared__ int sh[RMAX];
    for (int i = tid; i < RMAX; i += 256) sh[i] = 0;
    __syncthreads();
    const int base = b * 2048;
#pragma unroll
    for (int k = 0; k < 8; ++k) {
        const int e = base + k * 256 + tid;
        if (e < E) atomicAdd(&sh[__ldg(rels + e)], 1);
    }
    __syncthreads();
    for (int i = tid; i < RMAX; i += 256) {
        const int v = sh[i];
        if (v) atomicAdd(&g_c.cnt[i], v);
    }
    __threadfence();
    __syncthreads();
    __shared__ int s_last;
    if (tid == 0)
        s_last = (atomicAdd(&g_c.done, 1) == nbHist - 1);
    __syncthreads();
    if (s_last) {                                   // --- last block: scan ---
        __shared__ int buf[RMAX];
        const int c = atomicAdd(&g_c.cnt[tid], 0);  // coherent read
        buf[tid] = c;
        __syncthreads();
#pragma unroll
        for (int d = 1; d < RMAX; d <<= 1) {
            const int v = (tid >= d) ? buf[tid - d] : 0;
            __syncthreads();
            buf[tid] += v;
            __syncthreads();
        }
        if (tid == 0) g_off[0] = 0;
        g_off[tid + 1] = buf[tid];
        g_cur[tid]     = buf[tid] - c;              // exclusive
    }
}

// ---- launch 2: counting-sort scatter | zero out ----------------------------------
__global__ void __launch_bounds__(256)
k_scat(const int* __restrict__ edges,  // [2,E]
       const int* __restrict__ rels,   // [E]
       float*     __restrict__ out,
       int E, int nbHist, int out_sz)
{
    int b = blockIdx.x;
    const int tid = threadIdx.x;

    if (b >= nbHist) {                              // --- zero out blocks ---
        b -= nbHist;
        const int i0 = (b * 256 + tid) * 4;
        if (i0 + 3 < out_sz)
            *(float4*)(out + i0) = make_float4(0.f, 0.f, 0.f, 0.f);
        else
            for (int i = i0; i < out_sz; ++i) out[i] = 0.f;
        return;
    }

    __shared__ int h[RMAX];
    __shared__ int cur[RMAX];
    for (int i = tid; i < RMAX; i += 256) h[i] = 0;
    __syncthreads();
    const int base = b * 2048;
    int rr[8];
#pragma unroll
    for (int k = 0; k < 8; ++k) {
        const int e = base + k * 256 + tid;
        rr[k] = (e < E) ? __ldg(rels + e) : -1;
        if (rr[k] >= 0) atomicAdd(&h[rr[k]], 1);
    }
    __syncthreads();
    for (int i = tid; i < RMAX; i += 256) {
        const int v = h[i];
        cur[i] = v ? atomicAdd(&g_cur[i], v) : 0;
    }
    __syncthreads();
#pragma unroll
    for (int k = 0; k < 8; ++k) {
        if (rr[k] >= 0) {
            const int e   = base + k * 256 + tid;
            const int pos = atomicAdd(&cur[rr[k]], 1);
            g_edge[pos] = make_int4(__ldg(edges + e), __ldg(edges + E + e), e, 0);
        }
    }
}

// ---- launch 3: fused attention + message + self-loop, red.v4, ILP = 4 -----------
__global__ void __launch_bounds__(256)
k_main(const float* __restrict__ node_feat,
       const float* __restrict__ ttr,   // [E,32]
       const float* __restrict__ tre,   // [E,32]
       const float* __restrict__ A_w,   // [32,128]
       const float* __restrict__ B_w,   // [32]
       const float* __restrict__ B_b,   // [1]
       float*       __restrict__ out)
{
    const int r     = blockIdx.x;
    const int start = __ldg(&g_off[r]);
    const int end   = __ldg(&g_off[r + 1]);

    const int tid  = threadIdx.x;
    const int lane = tid & 31;

    // are/atr coefficients packed as f32x2 in smem: row = output lane
    __shared__ u64 sAre[32 * 17];
    __shared__ u64 sAtr[32 * 17];
    if (start < end) {
        for (int idx = tid; idx < 32 * 16; idx += 256) {
            const int row = idx >> 4, i = idx & 15;
            sAre[row * 17 + i] = pk2(__ldg(A_w + row * 128 + 64 + 2*i),
                                     __ldg(A_w + row * 128 + 64 + 2*i + 1));
            sAtr[row * 17 + i] = pk2(__ldg(A_w + row * 128 + 96 + 2*i),
                                     __ldg(A_w + row * 128 + 96 + 2*i + 1));
        }
        __syncthreads();
    }
    if (start >= end) return;

    u64 rwcP[16];                       // column `lane` of rel_w[r], packed pairs
#pragma unroll
    for (int i = 0; i < 16; ++i)
        rwcP[i] = pk2(__ldg(&g_relw[r * 1024 + (2*i)   * 32 + lane]),
                      __ldg(&g_relw[r * 1024 + (2*i+1) * 32 + lane]));

    const float bw = __ldg(B_w + lane);
    const float bb = __ldg(B_b);

    const int w = blockIdx.y * 8 + (tid >> 5);
    const int W = gridDim.y * 8;

    for (int i0 = start + w * 4; i0 < end; i0 += W * 4) {
        int ss[4], tt[4], ee[4];
#pragma unroll
        for (int k = 0; k < 4; ++k) {
            const int ii = min(i0 + k, end - 1);    // always in-bounds
            const int4 e4 = __ldg(&g_edge[ii]);
            ss[k] = e4.x; tt[k] = e4.y; ee[k] = e4.z;
        }
        float hh[4], sl[4];
#pragma unroll
        for (int k = 0; k < 4; ++k) {
            const float2 hts = __ldg(&g_htsl[(size_t)tt[k] * 32 + lane]);
            hh[k] = __ldg(&g_hs[(size_t)ss[k] * 32 + lane]) + hts.x;
            sl[k] = hts.y;
        }

        u64 aacc[4] = {0ull, 0ull, 0ull, 0ull};
        u64 macc[4] = {0ull, 0ull, 0ull, 0ull};
#pragma unroll
        for (int c = 0; c < 8; ++c) {
            const u64 a0 = sAre[lane * 17 + 2*c];
            const u64 a1 = sAre[lane * 17 + 2*c + 1];
            const u64 t0 = sAtr[lane * 17 + 2*c];
            const u64 t1 = sAtr[lane * 17 + 2*c + 1];
#pragma unroll
            for (int k = 0; k < 4; ++k) {
                ulonglong2 X = __ldg((const ulonglong2*)(tre + (size_t)ee[k] * 32) + c);
                ulonglong2 Y = __ldg((const ulonglong2*)(ttr + (size_t)ee[k] * 32) + c);
                ulonglong2 F = __ldg((const ulonglong2*)(node_feat + (size_t)ss[k] * 32) + c);
                fma2(aacc[k], X.x, a0);  fma2(aacc[k], X.y, a1);
                fma2(aacc[k], Y.x, t0);  fma2(aacc[k], Y.y, t1);
                fma2(macc[k], F.x, rwcP[2*c]);
                fma2(macc[k], F.y, rwcP[2*c+1]);
            }
        }
        float p[4];
#pragma unroll
        for (int k = 0; k < 4; ++k)
            p[k] = fmaxf(hh[k] + upk_sum(aacc[k]), 0.f) * bw;
#pragma unroll
        for (int o = 16; o; o >>= 1) {
#pragma unroll
            for (int k = 0; k < 4; ++k)
                p[k] += __shfl_xor_sync(0xffffffffu, p[k], o);
        }
        float v[4];
#pragma unroll
        for (int k = 0; k < 4; ++k) {
            const float att = 1.f / (1.f + __expf(-(p[k] + bb)));
            v[k] = fmaf(upk_sum(macc[k]), att, sl[k]);
        }

        // all 32 lanes issue one red.v4: lane group k = edge k, 8 lanes each
        const int kk = lane >> 3;           // which edge this lane stores
        const int g0 = (lane & 7) * 4;      // feature offset
        float q0 = 0.f, q1 = 0.f, q2 = 0.f, q3 = 0.f;
#pragma unroll
        for (int k = 0; k < 4; ++k) {
            float a  = __shfl_sync(0xffffffffu, v[k], g0 + 0);
            float bq = __shfl_sync(0xffffffffu, v[k], g0 + 1);
            float cq = __shfl_sync(0xffffffffu, v[k], g0 + 2);
            float dq = __shfl_sync(0xffffffffu, v[k], g0 + 3);
            if (kk == k) { q0 = a; q1 = bq; q2 = cq; q3 = dq; }
        }
        if (i0 + kk < end) {
            float* p_ = out + (size_t)tt[kk] * 32 + g0;
            asm volatile("red.global.add.v4.f32 [%0], {%1, %2, %3, %4};"
                         :: "l"(p_), "f"(q0), "f"(q1), "f"(q2), "f"(q3) : "memory");
        }
    }
}

extern "C" void kernel_launch(void* const* d_in, const int* in_sizes, int n_in,
                              void* d_out, int out_size)
{
    const float* node_feat = (const float*)d_in[0];
    const float* ttr       = (const float*)d_in[1];
    const float* tre       = (const float*)d_in[2];
    const float* weight    = (const float*)d_in[3];
    const float* w_comp    = (const float*)d_in[4];
    const float* slw       = (const float*)d_in[5];
    const float* A_w       = (const float*)d_in[6];
    const float* A_b       = (const float*)d_in[7];
    const float* B_w       = (const float*)d_in[8];
    const float* B_b       = (const float*)d_in[9];
    const int*   edges     = (const int*)d_in[10];
    const int*   rels      = (const int*)d_in[11];
    float* out = (float*)d_out;

    const int E  = in_sizes[11];
    const int N  = in_sizes[0] / 32;
    const int NB = in_sizes[3] / 1024;
    const int R  = in_sizes[4] / NB;

    const int nbNode = (N + 63) / 64;
    const int nbHist = (E + 2047) / 2048;
    const int nbZero = (out_size + 1023) / 1024;   // 256 thr * 4 floats

    void* cptr = nullptr;
    cudaGetSymbolAddress(&cptr, g_c);
    cudaMemsetAsync(cptr, 0, sizeof(Counters));

    k_pre<<<R + nbNode + nbHist, 256>>>(weight, w_comp, node_feat, A_w, A_b,
                                        slw, rels, NB, R, N, E, nbNode, nbHist);
    k_scat<<<nbHist + nbZero, 256>>>(edges, rels, out, E, nbHist, out_size);
    k_main<<<dim3(R, 10), 256>>>(node_feat, ttr, tre, A_w, B_w, B_b, out);
}